// round 1
// baseline (speedup 1.0000x reference)
#include <cuda_runtime.h>
#include <math.h>

#define BB     2
#define HWP    16384      // H*W
#define CO     128
#define CLI    256
#define CIM    512
#define CHUNKP 2048
#define NCHUNK 8
#define EPSBN  1e-5f
#define SCALE  0.08838834764831845f   // 1/sqrt(128)

// Scratch: projections stored pixel-major [b][p][c] (c contiguous, 128 floats/row)
__device__ float g_lidar_proj[BB * HWP * CO];
__device__ float g_image_proj[BB * HWP * CO];

// ---------------------------------------------------------------------------
// Projection: Y[b,p,o] = relu( (sum_c W[o,c] * X[b,c,p] - mean[o])*scale[o] + beta[o] )
// grid (HWP/128, B), block 256.  Block tile: 128 pixels x 128 out-channels.
// ---------------------------------------------------------------------------
template<int CIN>
__global__ void proj_kernel(const float* __restrict__ x,     // [B][CIN][HWP]
                            const float* __restrict__ w,     // [CO][CIN]
                            const float* __restrict__ gamma,
                            const float* __restrict__ beta,
                            const float* __restrict__ mean,
                            const float* __restrict__ var,
                            float* __restrict__ out)         // [B][HWP][CO]
{
    const int LD = 132;
    __shared__ float Xs[32 * LD];   // Xs[k][p]
    __shared__ float Ws[32 * LD];   // Ws[k][o]

    const int tid = threadIdx.x;
    const int tx  = tid & 15;       // o dimension (16 x 8 = 128)
    const int ty  = tid >> 4;       // p dimension (16 x 8 = 128)
    const int bb  = blockIdx.y;
    const int p0  = blockIdx.x * 128;

    float acc[8][8];
#pragma unroll
    for (int i = 0; i < 8; i++)
#pragma unroll
        for (int j = 0; j < 8; j++) acc[i][j] = 0.f;

    const float* xb = x + (size_t)bb * CIN * HWP;

    for (int c0 = 0; c0 < CIN; c0 += 32) {
        // load X tile: 32 c-rows x 128 pixels (1024 float4, 4/thread)
#pragma unroll
        for (int t = 0; t < 4; t++) {
            int lin = tid + t * 256;
            int row = lin >> 5;          // 0..31 (c)
            int c4  = lin & 31;          // 0..31 (float4 along p)
            float4 v = *(const float4*)&xb[(size_t)(c0 + row) * HWP + p0 + c4 * 4];
            *(float4*)&Xs[row * LD + c4 * 4] = v;
        }
        // load W tile transposed: Ws[k][o] = w[o][c0+k]
#pragma unroll
        for (int t = 0; t < 4; t++) {
            int lin = tid + t * 256;
            int o   = lin >> 3;          // 0..127
            int kc4 = lin & 7;           // 0..7
            float4 v = *(const float4*)&w[(size_t)o * CIN + c0 + kc4 * 4];
            Ws[(kc4 * 4 + 0) * LD + o] = v.x;
            Ws[(kc4 * 4 + 1) * LD + o] = v.y;
            Ws[(kc4 * 4 + 2) * LD + o] = v.z;
            Ws[(kc4 * 4 + 3) * LD + o] = v.w;
        }
        __syncthreads();

#pragma unroll 8
        for (int k = 0; k < 32; k++) {
            float4 a0 = *(const float4*)&Xs[k * LD + ty * 8];
            float4 a1 = *(const float4*)&Xs[k * LD + ty * 8 + 4];
            float4 b0 = *(const float4*)&Ws[k * LD + tx * 8];
            float4 b1 = *(const float4*)&Ws[k * LD + tx * 8 + 4];
            float av[8] = {a0.x, a0.y, a0.z, a0.w, a1.x, a1.y, a1.z, a1.w};
            float bv[8] = {b0.x, b0.y, b0.z, b0.w, b1.x, b1.y, b1.z, b1.w};
#pragma unroll
            for (int i = 0; i < 8; i++)
#pragma unroll
                for (int j = 0; j < 8; j++)
                    acc[i][j] = fmaf(av[i], bv[j], acc[i][j]);
        }
        __syncthreads();
    }

    // BN + ReLU epilogue, store pixel-major [b][p][o], vectorized float4
    float scj[8], shj[8];
#pragma unroll
    for (int j = 0; j < 8; j++) {
        int o = tx * 8 + j;
        float s = gamma[o] * rsqrtf(var[o] + EPSBN);
        scj[j] = s;
        shj[j] = beta[o] - mean[o] * s;
    }
#pragma unroll
    for (int i = 0; i < 8; i++) {
        int p = p0 + ty * 8 + i;
        float* dst = out + ((size_t)bb * HWP + p) * CO + tx * 8;
        float4 v0, v1;
        v0.x = fmaxf(fmaf(acc[i][0], scj[0], shj[0]), 0.f);
        v0.y = fmaxf(fmaf(acc[i][1], scj[1], shj[1]), 0.f);
        v0.z = fmaxf(fmaf(acc[i][2], scj[2], shj[2]), 0.f);
        v0.w = fmaxf(fmaf(acc[i][3], scj[3], shj[3]), 0.f);
        v1.x = fmaxf(fmaf(acc[i][4], scj[4], shj[4]), 0.f);
        v1.y = fmaxf(fmaf(acc[i][5], scj[5], shj[5]), 0.f);
        v1.z = fmaxf(fmaf(acc[i][6], scj[6], shj[6]), 0.f);
        v1.w = fmaxf(fmaf(acc[i][7], scj[7], shj[7]), 0.f);
        *(float4*)&dst[0] = v0;
        *(float4*)&dst[4] = v1;
    }
}

// ---------------------------------------------------------------------------
// Flash attention over one 64-row q tile of one (b, chunk), plus final blend.
// grid (32, NCHUNK, B), block 256.  TQ=64, TK=64, D=128.
// out[b][c][p] = w0*image_proj + w1*(softmax(QK^T/sqrt(C)) K)
// ---------------------------------------------------------------------------
#define QK_LD 132
#define PS_LD 67
#define ATTN_SMEM ((2 * 64 * QK_LD + 64 * PS_LD) * 4)

__global__ void attn_kernel(const float* __restrict__ imgp,  // [B][HWP][CO]
                            const float* __restrict__ lidp,  // [B][HWP][CO]
                            const float* __restrict__ mw,    // [2]
                            float* __restrict__ out)         // [B][CO][HWP]
{
    extern __shared__ float sm[];
    float* Qs = sm;                      // 64 x QK_LD  (image_proj rows)
    float* Ks = sm + 64 * QK_LD;         // 64 x QK_LD  (lidar_proj rows; reused as Os)
    float* Ps = sm + 2 * 64 * QK_LD;     // 64 x PS_LD

    const int tid   = threadIdx.x;
    const int tx    = tid & 15;
    const int ty    = tid >> 4;
    const int qtile = blockIdx.x;
    const int chunk = blockIdx.y;
    const int bb    = blockIdx.z;
    const int pq0   = chunk * CHUNKP + qtile * 64;

    // load Q tile (8 float4 / thread)
#pragma unroll
    for (int t = 0; t < 8; t++) {
        int lin = tid + t * 256;
        int row = lin >> 5;
        int c4  = lin & 31;
        float4 v = *(const float4*)&imgp[((size_t)bb * HWP + pq0 + row) * CO + c4 * 4];
        *(float4*)&Qs[row * QK_LD + c4 * 4] = v;
    }

    float oacc[4][8];
    float m[4], l[4];
#pragma unroll
    for (int i = 0; i < 4; i++) {
        m[i] = -1e30f; l[i] = 0.f;
#pragma unroll
        for (int j = 0; j < 8; j++) oacc[i][j] = 0.f;
    }

    for (int kt = 0; kt < CHUNKP / 64; kt++) {
        const int pk0 = chunk * CHUNKP + kt * 64;
        // load K tile
#pragma unroll
        for (int t = 0; t < 8; t++) {
            int lin = tid + t * 256;
            int row = lin >> 5;
            int c4  = lin & 31;
            float4 v = *(const float4*)&lidp[((size_t)bb * HWP + pk0 + row) * CO + c4 * 4];
            *(float4*)&Ks[row * QK_LD + c4 * 4] = v;
        }
        __syncthreads();

        // S = Q . K^T  (thread rows ty+16i, cols tx+16j)
        float s[4][4];
#pragma unroll
        for (int i = 0; i < 4; i++)
#pragma unroll
            for (int j = 0; j < 4; j++) s[i][j] = 0.f;

#pragma unroll 4
        for (int kk = 0; kk < 128; kk += 4) {
            float4 q0 = *(const float4*)&Qs[(ty +  0) * QK_LD + kk];
            float4 q1 = *(const float4*)&Qs[(ty + 16) * QK_LD + kk];
            float4 q2 = *(const float4*)&Qs[(ty + 32) * QK_LD + kk];
            float4 q3 = *(const float4*)&Qs[(ty + 48) * QK_LD + kk];
#pragma unroll
            for (int j = 0; j < 4; j++) {
                float4 kv = *(const float4*)&Ks[(tx + 16 * j) * QK_LD + kk];
                s[0][j] += q0.x*kv.x + q0.y*kv.y + q0.z*kv.z + q0.w*kv.w;
                s[1][j] += q1.x*kv.x + q1.y*kv.y + q1.z*kv.z + q1.w*kv.w;
                s[2][j] += q2.x*kv.x + q2.y*kv.y + q2.z*kv.z + q2.w*kv.w;
                s[3][j] += q3.x*kv.x + q3.y*kv.y + q3.z*kv.z + q3.w*kv.w;
            }
        }

        // online softmax update
#pragma unroll
        for (int i = 0; i < 4; i++) {
#pragma unroll
            for (int j = 0; j < 4; j++) s[i][j] *= SCALE;
            float tmax = fmaxf(fmaxf(s[i][0], s[i][1]), fmaxf(s[i][2], s[i][3]));
            tmax = fmaxf(tmax, __shfl_xor_sync(0xffffffffu, tmax, 1));
            tmax = fmaxf(tmax, __shfl_xor_sync(0xffffffffu, tmax, 2));
            tmax = fmaxf(tmax, __shfl_xor_sync(0xffffffffu, tmax, 4));
            tmax = fmaxf(tmax, __shfl_xor_sync(0xffffffffu, tmax, 8));
            float mnew = fmaxf(m[i], tmax);
            float corr = __expf(m[i] - mnew);
            float psum = 0.f;
#pragma unroll
            for (int j = 0; j < 4; j++) {
                float p = __expf(s[i][j] - mnew);
                Ps[(ty + 16 * i) * PS_LD + tx + 16 * j] = p;
                psum += p;
            }
            psum += __shfl_xor_sync(0xffffffffu, psum, 1);
            psum += __shfl_xor_sync(0xffffffffu, psum, 2);
            psum += __shfl_xor_sync(0xffffffffu, psum, 4);
            psum += __shfl_xor_sync(0xffffffffu, psum, 8);
            l[i] = l[i] * corr + psum;
            m[i] = mnew;
#pragma unroll
            for (int j = 0; j < 8; j++) oacc[i][j] *= corr;
        }
        __syncthreads();

        // O += P . K   (thread cols tx*8 .. tx*8+7)
#pragma unroll 2
        for (int j = 0; j < 64; j++) {
            float p0 = Ps[(ty +  0) * PS_LD + j];
            float p1 = Ps[(ty + 16) * PS_LD + j];
            float p2 = Ps[(ty + 32) * PS_LD + j];
            float p3 = Ps[(ty + 48) * PS_LD + j];
            float4 k0 = *(const float4*)&Ks[j * QK_LD + tx * 8];
            float4 k1 = *(const float4*)&Ks[j * QK_LD + tx * 8 + 4];
            oacc[0][0]+=p0*k0.x; oacc[0][1]+=p0*k0.y; oacc[0][2]+=p0*k0.z; oacc[0][3]+=p0*k0.w;
            oacc[0][4]+=p0*k1.x; oacc[0][5]+=p0*k1.y; oacc[0][6]+=p0*k1.z; oacc[0][7]+=p0*k1.w;
            oacc[1][0]+=p1*k0.x; oacc[1][1]+=p1*k0.y; oacc[1][2]+=p1*k0.z; oacc[1][3]+=p1*k0.w;
            oacc[1][4]+=p1*k1.x; oacc[1][5]+=p1*k1.y; oacc[1][6]+=p1*k1.z; oacc[1][7]+=p1*k1.w;
            oacc[2][0]+=p2*k0.x; oacc[2][1]+=p2*k0.y; oacc[2][2]+=p2*k0.z; oacc[2][3]+=p2*k0.w;
            oacc[2][4]+=p2*k1.x; oacc[2][5]+=p2*k1.y; oacc[2][6]+=p2*k1.z; oacc[2][7]+=p2*k1.w;
            oacc[3][0]+=p3*k0.x; oacc[3][1]+=p3*k0.y; oacc[3][2]+=p3*k0.z; oacc[3][3]+=p3*k0.w;
            oacc[3][4]+=p3*k1.x; oacc[3][5]+=p3*k1.y; oacc[3][6]+=p3*k1.z; oacc[3][7]+=p3*k1.w;
        }
        __syncthreads();
    }

    // blend with image_proj, stage into Ks (free now) for coalesced output
    float e0 = __expf(mw[0]), e1 = __expf(mw[1]);
    float w0 = e0 / (e0 + e1), w1 = e1 / (e0 + e1);
#pragma unroll
    for (int i = 0; i < 4; i++) {
        int r = ty + 16 * i;
        float invl = 1.f / l[i];
#pragma unroll
        for (int j = 0; j < 8; j++) {
            int c = tx * 8 + j;
            float fused = oacc[i][j] * invl;
            Ks[r * QK_LD + c] = w0 * Qs[r * QK_LD + c] + w1 * fused;
        }
    }
    __syncthreads();

    // write out[b][c][pq0+pi], coalesced along p
    float* ob = out + (size_t)bb * CO * HWP;
#pragma unroll
    for (int t = 0; t < 32; t++) {
        int lin = tid + t * 256;          // 0..8191
        int c   = lin >> 6;               // 0..127
        int pi  = lin & 63;               // 0..63
        ob[(size_t)c * HWP + pq0 + pi] = Ks[pi * QK_LD + c];
    }
}

// ---------------------------------------------------------------------------
extern "C" void kernel_launch(void* const* d_in, const int* in_sizes, int n_in,
                              void* d_out, int out_size)
{
    const float* lidar_x = (const float*)d_in[0];
    const float* image_x = (const float*)d_in[1];
    const float* lw  = (const float*)d_in[2];
    const float* lg  = (const float*)d_in[3];
    const float* lb  = (const float*)d_in[4];
    const float* lm  = (const float*)d_in[5];
    const float* lv  = (const float*)d_in[6];
    const float* iw  = (const float*)d_in[7];
    const float* ig  = (const float*)d_in[8];
    const float* ib  = (const float*)d_in[9];
    const float* im  = (const float*)d_in[10];
    const float* iv  = (const float*)d_in[11];
    const float* mw  = (const float*)d_in[12];
    float* out = (float*)d_out;

    float *lp = nullptr, *ip = nullptr;
    cudaGetSymbolAddress((void**)&lp, g_lidar_proj);
    cudaGetSymbolAddress((void**)&ip, g_image_proj);
    cudaFuncSetAttribute(attn_kernel, cudaFuncAttributeMaxDynamicSharedMemorySize, ATTN_SMEM);

    dim3 pgrid(HWP / 128, BB);
    proj_kernel<CLI><<<pgrid, 256>>>(lidar_x, lw, lg, lb, lm, lv, lp);
    proj_kernel<CIM><<<pgrid, 256>>>(image_x, iw, ig, ib, im, iv, ip);

    dim3 agrid(CHUNKP / 64, NCHUNK, BB);
    attn_kernel<<<agrid, 256, ATTN_SMEM>>>(ip, lp, mw, out);
}

// round 2
// speedup vs baseline: 2.7525x; 2.7525x over previous
#include <cuda_runtime.h>
#include <math.h>
#include <stdint.h>

#define BB     2
#define HWP    16384
#define CO     128
#define CLI    256
#define CIM    512
#define CHUNKP 2048
#define NCHUNK 8
#define EPSBN  1e-5f
#define SCALE  0.08838834764831845f   // 1/sqrt(128)

// Scratch: projections pixel-major [b][p][c]
__device__ float g_lidar_proj[BB * HWP * CO];
__device__ float g_image_proj[BB * HWP * CO];

// ---------------------------------------------------------------------------
// helpers: tf32 convert + m16n8k8 tf32 mma
// ---------------------------------------------------------------------------
__device__ __forceinline__ uint32_t f2tf(float x) {
    uint32_t u;
    asm("cvt.rna.tf32.f32 %0, %1;" : "=r"(u) : "f"(x));
    return u;
}
__device__ __forceinline__ float f2tff(float x) { return __uint_as_float(f2tf(x)); }

__device__ __forceinline__ void mma_tf32(float* c,
                                         uint32_t a0, uint32_t a1, uint32_t a2, uint32_t a3,
                                         uint32_t b0, uint32_t b1) {
    asm volatile(
        "mma.sync.aligned.m16n8k8.row.col.f32.tf32.tf32.f32 "
        "{%0,%1,%2,%3}, {%4,%5,%6,%7}, {%8,%9}, {%0,%1,%2,%3};"
        : "+f"(c[0]), "+f"(c[1]), "+f"(c[2]), "+f"(c[3])
        : "r"(a0), "r"(a1), "r"(a2), "r"(a3), "r"(b0), "r"(b1));
}

#define U(x) __float_as_uint(x)

// ---------------------------------------------------------------------------
// Projection (tf32 MMA): Y[b,p,o] = relu(BN(sum_c W[o,c]*X[b,c,p]))
// grid (HWP/128, B), 256 threads (8 warps). Tile: 128 px x 128 o.
// Warp w: pixels [32*(w>>1), +32), outs [64*(w&1), +64). m2 n8 per k8-step.
// ---------------------------------------------------------------------------
#define PLD 132
#define PROJ_SMEM (128 * PLD * 4)   // staging overlays Xs+Ws (2*32*132 < 128*132)

template<int CIN>
__global__ __launch_bounds__(256)
void proj_kernel(const float* __restrict__ x,     // [B][CIN][HWP]
                 const float* __restrict__ w,     // [CO][CIN]
                 const float* __restrict__ gamma,
                 const float* __restrict__ beta,
                 const float* __restrict__ mean,
                 const float* __restrict__ var,
                 float* __restrict__ out)         // [B][HWP][CO]
{
    extern __shared__ float psm[];
    float* Xs = psm;                 // [32][PLD]  Xs[c][p]
    float* Ws = psm + 32 * PLD;      // [32][PLD]  Ws[c][o]

    const int tid  = threadIdx.x;
    const int wid  = tid >> 5;
    const int lane = tid & 31;
    const int g    = lane >> 2;
    const int t4   = lane & 3;
    const int pb   = (wid >> 1) * 32;
    const int ob   = (wid & 1) * 64;
    const int bb   = blockIdx.y;
    const int p0   = blockIdx.x * 128;

    float acc[2][8][4];
#pragma unroll
    for (int mt = 0; mt < 2; mt++)
#pragma unroll
        for (int nt = 0; nt < 8; nt++)
#pragma unroll
            for (int i = 0; i < 4; i++) acc[mt][nt][i] = 0.f;

    const float* xb = x + (size_t)bb * CIN * HWP;

    for (int c0 = 0; c0 < CIN; c0 += 32) {
        __syncthreads();
        // X tile: 32 c-rows x 128 px, tf32-converted
#pragma unroll
        for (int t = 0; t < 4; t++) {
            int lin = tid + t * 256;
            int row = lin >> 5;
            int c4  = lin & 31;
            float4 v = *(const float4*)&xb[(size_t)(c0 + row) * HWP + p0 + c4 * 4];
            v.x = f2tff(v.x); v.y = f2tff(v.y); v.z = f2tff(v.z); v.w = f2tff(v.w);
            *(float4*)&Xs[row * PLD + c4 * 4] = v;
        }
        // W tile transposed: Ws[c][o], tf32-converted
#pragma unroll
        for (int t = 0; t < 4; t++) {
            int lin = tid + t * 256;
            int o   = lin >> 3;
            int kc4 = lin & 7;
            float4 v = *(const float4*)&w[(size_t)o * CIN + c0 + kc4 * 4];
            Ws[(kc4 * 4 + 0) * PLD + o] = f2tff(v.x);
            Ws[(kc4 * 4 + 1) * PLD + o] = f2tff(v.y);
            Ws[(kc4 * 4 + 2) * PLD + o] = f2tff(v.z);
            Ws[(kc4 * 4 + 3) * PLD + o] = f2tff(v.w);
        }
        __syncthreads();

#pragma unroll
        for (int ks = 0; ks < 4; ks++) {
            int kc = ks * 8;
            // A fragments: rows pb+16*mt+{g,g+8}, cols kc+{t4,t4+4}
            uint32_t a[2][4];
#pragma unroll
            for (int mt = 0; mt < 2; mt++) {
                int pr = pb + 16 * mt;
                a[mt][0] = U(Xs[(kc + t4) * PLD + pr + g]);
                a[mt][1] = U(Xs[(kc + t4) * PLD + pr + g + 8]);
                a[mt][2] = U(Xs[(kc + t4 + 4) * PLD + pr + g]);
                a[mt][3] = U(Xs[(kc + t4 + 4) * PLD + pr + g + 8]);
            }
#pragma unroll
            for (int nt = 0; nt < 8; nt++) {
                uint32_t b0 = U(Ws[(kc + t4) * PLD + ob + nt * 8 + g]);
                uint32_t b1 = U(Ws[(kc + t4 + 4) * PLD + ob + nt * 8 + g]);
                mma_tf32(acc[0][nt], a[0][0], a[0][1], a[0][2], a[0][3], b0, b1);
                mma_tf32(acc[1][nt], a[1][0], a[1][1], a[1][2], a[1][3], b0, b1);
            }
        }
    }

    // epilogue: BN + ReLU -> staging (overlay) -> coalesced f4 store
    __syncthreads();
    float* Fs = psm;   // [128][PLD]
#pragma unroll
    for (int mt = 0; mt < 2; mt++) {
#pragma unroll
        for (int nt = 0; nt < 8; nt++) {
            int c  = ob + nt * 8 + 2 * t4;
            float s0 = gamma[c]     * rsqrtf(var[c]     + EPSBN);
            float s1 = gamma[c + 1] * rsqrtf(var[c + 1] + EPSBN);
            float h0 = beta[c]     - mean[c]     * s0;
            float h1 = beta[c + 1] - mean[c + 1] * s1;
            int r = pb + 16 * mt + g;
            float2 v0, v1;
            v0.x = fmaxf(fmaf(acc[mt][nt][0], s0, h0), 0.f);
            v0.y = fmaxf(fmaf(acc[mt][nt][1], s1, h1), 0.f);
            v1.x = fmaxf(fmaf(acc[mt][nt][2], s0, h0), 0.f);
            v1.y = fmaxf(fmaf(acc[mt][nt][3], s1, h1), 0.f);
            *(float2*)&Fs[r * PLD + c]       = v0;
            *(float2*)&Fs[(r + 8) * PLD + c] = v1;
        }
    }
    __syncthreads();
#pragma unroll
    for (int t = 0; t < 16; t++) {
        int lin = tid + t * 256;
        int row = lin >> 5;
        int c4  = lin & 31;
        float4 v = *(const float4*)&Fs[row * PLD + c4 * 4];
        *(float4*)&out[((size_t)bb * HWP + p0 + row) * CO + c4 * 4] = v;
    }
}

// ---------------------------------------------------------------------------
// Flash attention, tf32 MMA. TQ=64, TK=64, D=128. 128 threads (4 warps),
// warp owns 16 q rows. grid (CHUNKP/64, NCHUNK, B).
// ---------------------------------------------------------------------------
#define QK_LD 132
#define PS_LD 68
#define ATTN_SMEM ((2 * 64 * QK_LD + 64 * PS_LD) * 4)

__global__ __launch_bounds__(128)
void attn_kernel(const float* __restrict__ imgp,  // [B][HWP][CO]
                 const float* __restrict__ lidp,  // [B][HWP][CO]
                 const float* __restrict__ mw,
                 float* __restrict__ out)         // [B][CO][HWP]
{
    extern __shared__ float sm[];
    float* Qs = sm;                      // [64][QK_LD]  scaled tf32 Q
    float* Ks = sm + 64 * QK_LD;         // [64][QK_LD]  tf32 K
    float* Ps = sm + 2 * 64 * QK_LD;     // [64][PS_LD]  tf32 P

    const int tid  = threadIdx.x;
    const int wid  = tid >> 5;
    const int lane = tid & 31;
    const int g    = lane >> 2;
    const int t4   = lane & 3;
    const int qb   = wid * 16;
    const int chunk = blockIdx.y;
    const int bb    = blockIdx.z;
    const int pq0   = chunk * CHUNKP + blockIdx.x * 64;

    // Q tile: pre-scaled by 1/sqrt(C), tf32
#pragma unroll
    for (int t = 0; t < 16; t++) {
        int lin = tid + t * 128;
        int row = lin >> 5;
        int c4  = lin & 31;
        float4 v = *(const float4*)&imgp[((size_t)bb * HWP + pq0 + row) * CO + c4 * 4];
        v.x = f2tff(v.x * SCALE); v.y = f2tff(v.y * SCALE);
        v.z = f2tff(v.z * SCALE); v.w = f2tff(v.w * SCALE);
        *(float4*)&Qs[row * QK_LD + c4 * 4] = v;
    }

    float oacc[16][4];
#pragma unroll
    for (int nt = 0; nt < 16; nt++)
#pragma unroll
        for (int i = 0; i < 4; i++) oacc[nt][i] = 0.f;
    float m0 = -1e30f, m1 = -1e30f, l0 = 0.f, l1 = 0.f;

    for (int kt = 0; kt < CHUNKP / 64; kt++) {
        __syncthreads();
        const int pk0 = chunk * CHUNKP + kt * 64;
#pragma unroll
        for (int t = 0; t < 16; t++) {
            int lin = tid + t * 128;
            int row = lin >> 5;
            int c4  = lin & 31;
            float4 v = *(const float4*)&lidp[((size_t)bb * HWP + pk0 + row) * CO + c4 * 4];
            v.x = f2tff(v.x); v.y = f2tff(v.y); v.z = f2tff(v.z); v.w = f2tff(v.w);
            *(float4*)&Ks[row * QK_LD + c4 * 4] = v;
        }
        __syncthreads();

        // ---- S = Q . K^T : warp computes rows [qb,qb+16) x 64 cols ----
        float sc[8][4];
#pragma unroll
        for (int nt = 0; nt < 8; nt++)
#pragma unroll
            for (int i = 0; i < 4; i++) sc[nt][i] = 0.f;

#pragma unroll
        for (int ks = 0; ks < 16; ks++) {
            int kc = ks * 8;
            uint32_t a0 = U(Qs[(qb + g) * QK_LD + kc + t4]);
            uint32_t a1 = U(Qs[(qb + g + 8) * QK_LD + kc + t4]);
            uint32_t a2 = U(Qs[(qb + g) * QK_LD + kc + t4 + 4]);
            uint32_t a3 = U(Qs[(qb + g + 8) * QK_LD + kc + t4 + 4]);
#pragma unroll
            for (int nt = 0; nt < 8; nt++) {
                uint32_t b0 = U(Ks[(nt * 8 + g) * QK_LD + kc + t4]);
                uint32_t b1 = U(Ks[(nt * 8 + g) * QK_LD + kc + t4 + 4]);
                mma_tf32(sc[nt], a0, a1, a2, a3, b0, b1);
            }
        }

        // ---- online softmax (rows qb+g and qb+g+8; reduce over 4 t-lanes) ----
        float mx0 = -1e30f, mx1 = -1e30f;
#pragma unroll
        for (int nt = 0; nt < 8; nt++) {
            mx0 = fmaxf(mx0, fmaxf(sc[nt][0], sc[nt][1]));
            mx1 = fmaxf(mx1, fmaxf(sc[nt][2], sc[nt][3]));
        }
        mx0 = fmaxf(mx0, __shfl_xor_sync(0xffffffffu, mx0, 1));
        mx0 = fmaxf(mx0, __shfl_xor_sync(0xffffffffu, mx0, 2));
        mx1 = fmaxf(mx1, __shfl_xor_sync(0xffffffffu, mx1, 1));
        mx1 = fmaxf(mx1, __shfl_xor_sync(0xffffffffu, mx1, 2));
        float mn0 = fmaxf(m0, mx0), mn1 = fmaxf(m1, mx1);
        float cr0 = __expf(m0 - mn0), cr1 = __expf(m1 - mn1);
        m0 = mn0; m1 = mn1;
        float ps0 = 0.f, ps1 = 0.f;
#pragma unroll
        for (int nt = 0; nt < 8; nt++) {
            float p00 = __expf(sc[nt][0] - mn0);
            float p01 = __expf(sc[nt][1] - mn0);
            float p10 = __expf(sc[nt][2] - mn1);
            float p11 = __expf(sc[nt][3] - mn1);
            ps0 += p00 + p01; ps1 += p10 + p11;
            float2 v0 = make_float2(f2tff(p00), f2tff(p01));
            float2 v1 = make_float2(f2tff(p10), f2tff(p11));
            *(float2*)&Ps[(qb + g) * PS_LD + nt * 8 + 2 * t4]     = v0;
            *(float2*)&Ps[(qb + g + 8) * PS_LD + nt * 8 + 2 * t4] = v1;
        }
        ps0 += __shfl_xor_sync(0xffffffffu, ps0, 1);
        ps0 += __shfl_xor_sync(0xffffffffu, ps0, 2);
        ps1 += __shfl_xor_sync(0xffffffffu, ps1, 1);
        ps1 += __shfl_xor_sync(0xffffffffu, ps1, 2);
        l0 = l0 * cr0 + ps0;
        l1 = l1 * cr1 + ps1;
#pragma unroll
        for (int nt = 0; nt < 16; nt++) {
            oacc[nt][0] *= cr0; oacc[nt][1] *= cr0;
            oacc[nt][2] *= cr1; oacc[nt][3] *= cr1;
        }
        __syncthreads();

        // ---- O += P . K : rows [qb,qb+16) x 128 d-cols ----
#pragma unroll
        for (int ks = 0; ks < 8; ks++) {
            int kc = ks * 8;
            uint32_t a0 = U(Ps[(qb + g) * PS_LD + kc + t4]);
            uint32_t a1 = U(Ps[(qb + g + 8) * PS_LD + kc + t4]);
            uint32_t a2 = U(Ps[(qb + g) * PS_LD + kc + t4 + 4]);
            uint32_t a3 = U(Ps[(qb + g + 8) * PS_LD + kc + t4 + 4]);
#pragma unroll
            for (int nt = 0; nt < 16; nt++) {
                uint32_t b0 = U(Ks[(kc + t4) * QK_LD + nt * 8 + g]);
                uint32_t b1 = U(Ks[(kc + t4 + 4) * QK_LD + nt * 8 + g]);
                mma_tf32(oacc[nt], a0, a1, a2, a3, b0, b1);
            }
        }
    }

    // ---- blend epilogue: fused = O/l; out = w0*image + w1*fused ----
    float e0 = __expf(mw[0]), e1 = __expf(mw[1]);
    float w0 = e0 / (e0 + e1), w1 = e1 / (e0 + e1);
    float il0 = 1.f / l0, il1 = 1.f / l1;
    const float* imb0 = imgp + ((size_t)bb * HWP + pq0 + qb + g) * CO;
    const float* imb1 = imb0 + 8 * CO;
#pragma unroll
    for (int nt = 0; nt < 16; nt++) {
        int c = nt * 8 + 2 * t4;
        float2 i0 = *(const float2*)&imb0[c];
        float2 i1 = *(const float2*)&imb1[c];
        float2 v0, v1;
        v0.x = w0 * i0.x + w1 * oacc[nt][0] * il0;
        v0.y = w0 * i0.y + w1 * oacc[nt][1] * il0;
        v1.x = w0 * i1.x + w1 * oacc[nt][2] * il1;
        v1.y = w0 * i1.y + w1 * oacc[nt][3] * il1;
        *(float2*)&Qs[(qb + g) * QK_LD + c]     = v0;   // Qs reused as staging
        *(float2*)&Qs[(qb + g + 8) * QK_LD + c] = v1;
    }
    __syncthreads();

    float* ob = out + (size_t)bb * CO * HWP;
#pragma unroll
    for (int t = 0; t < 64; t++) {
        int lin = tid + t * 128;
        int c   = lin >> 6;
        int pi  = lin & 63;
        ob[(size_t)c * HWP + pq0 + pi] = Qs[pi * QK_LD + c];
    }
}

// ---------------------------------------------------------------------------
extern "C" void kernel_launch(void* const* d_in, const int* in_sizes, int n_in,
                              void* d_out, int out_size)
{
    const float* lidar_x = (const float*)d_in[0];
    const float* image_x = (const float*)d_in[1];
    const float* lw  = (const float*)d_in[2];
    const float* lg  = (const float*)d_in[3];
    const float* lb  = (const float*)d_in[4];
    const float* lm  = (const float*)d_in[5];
    const float* lv  = (const float*)d_in[6];
    const float* iw  = (const float*)d_in[7];
    const float* ig  = (const float*)d_in[8];
    const float* ib  = (const float*)d_in[9];
    const float* im  = (const float*)d_in[10];
    const float* iv  = (const float*)d_in[11];
    const float* mw  = (const float*)d_in[12];
    float* out = (float*)d_out;

    float *lp = nullptr, *ip = nullptr;
    cudaGetSymbolAddress((void**)&lp, g_lidar_proj);
    cudaGetSymbolAddress((void**)&ip, g_image_proj);
    cudaFuncSetAttribute(proj_kernel<CLI>, cudaFuncAttributeMaxDynamicSharedMemorySize, PROJ_SMEM);
    cudaFuncSetAttribute(proj_kernel<CIM>, cudaFuncAttributeMaxDynamicSharedMemorySize, PROJ_SMEM);
    cudaFuncSetAttribute(attn_kernel, cudaFuncAttributeMaxDynamicSharedMemorySize, ATTN_SMEM);

    dim3 pgrid(HWP / 128, BB);
    proj_kernel<CLI><<<pgrid, 256, PROJ_SMEM>>>(lidar_x, lw, lg, lb, lm, lv, lp);
    proj_kernel<CIM><<<pgrid, 256, PROJ_SMEM>>>(image_x, iw, ig, ib, im, iv, ip);

    dim3 agrid(CHUNKP / 64, NCHUNK, BB);
    attn_kernel<<<agrid, 128, ATTN_SMEM>>>(ip, lp, mw, out);
}

// round 3
// speedup vs baseline: 2.7580x; 1.0020x over previous
#include <cuda_runtime.h>
#include <math.h>
#include <stdint.h>

#define BB     2
#define HWP    16384
#define CO     128
#define CLI    256
#define CIM    512
#define CHUNKP 2048
#define NCHUNK 8
#define EPSBN  1e-5f
#define SCALE  0.08838834764831845f   // 1/sqrt(128)

// Scratch: projections pixel-major [b][p][c]
__device__ float g_lidar_proj[BB * HWP * CO];
__device__ float g_image_proj[BB * HWP * CO];

// ---------------------------------------------------------------------------
// helpers: tf32 convert + m16n8k8 tf32 mma
// ---------------------------------------------------------------------------
__device__ __forceinline__ uint32_t f2tf(float x) {
    uint32_t u;
    asm("cvt.rna.tf32.f32 %0, %1;" : "=r"(u) : "f"(x));
    return u;
}
__device__ __forceinline__ float f2tff(float x) { return __uint_as_float(f2tf(x)); }

__device__ __forceinline__ void mma_tf32(float* c,
                                         uint32_t a0, uint32_t a1, uint32_t a2, uint32_t a3,
                                         uint32_t b0, uint32_t b1) {
    asm volatile(
        "mma.sync.aligned.m16n8k8.row.col.f32.tf32.tf32.f32 "
        "{%0,%1,%2,%3}, {%4,%5,%6,%7}, {%8,%9}, {%0,%1,%2,%3};"
        : "+f"(c[0]), "+f"(c[1]), "+f"(c[2]), "+f"(c[3])
        : "r"(a0), "r"(a1), "r"(a2), "r"(a3), "r"(b0), "r"(b1));
}

#define U(x) __float_as_uint(x)

// ---------------------------------------------------------------------------
// Projection (tf32 MMA): Y[b,p,o] = relu(BN(sum_c W[o,c]*X[b,c,p]))
// grid (HWP/128, B), 256 threads (8 warps). Tile: 128 px x 128 o.
// Warp w: pixels [32*(w>>1), +32), outs [64*(w&1), +64). m2 n8 per k8-step.
// ---------------------------------------------------------------------------
#define PLD 132
#define PROJ_SMEM (128 * PLD * 4)   // staging overlays Xs+Ws (2*32*132 < 128*132)

template<int CIN>
__global__ __launch_bounds__(256)
void proj_kernel(const float* __restrict__ x,     // [B][CIN][HWP]
                 const float* __restrict__ w,     // [CO][CIN]
                 const float* __restrict__ gamma,
                 const float* __restrict__ beta,
                 const float* __restrict__ mean,
                 const float* __restrict__ var,
                 float* __restrict__ out)         // [B][HWP][CO]
{
    extern __shared__ float psm[];
    float* Xs = psm;                 // [32][PLD]  Xs[c][p]
    float* Ws = psm + 32 * PLD;      // [32][PLD]  Ws[c][o]

    const int tid  = threadIdx.x;
    const int wid  = tid >> 5;
    const int lane = tid & 31;
    const int g    = lane >> 2;
    const int t4   = lane & 3;
    const int pb   = (wid >> 1) * 32;
    const int ob   = (wid & 1) * 64;
    const int bb   = blockIdx.y;
    const int p0   = blockIdx.x * 128;

    float acc[2][8][4];
#pragma unroll
    for (int mt = 0; mt < 2; mt++)
#pragma unroll
        for (int nt = 0; nt < 8; nt++)
#pragma unroll
            for (int i = 0; i < 4; i++) acc[mt][nt][i] = 0.f;

    const float* xb = x + (size_t)bb * CIN * HWP;

    for (int c0 = 0; c0 < CIN; c0 += 32) {
        __syncthreads();
        // X tile: 32 c-rows x 128 px, tf32-converted
#pragma unroll
        for (int t = 0; t < 4; t++) {
            int lin = tid + t * 256;
            int row = lin >> 5;
            int c4  = lin & 31;
            float4 v = *(const float4*)&xb[(size_t)(c0 + row) * HWP + p0 + c4 * 4];
            v.x = f2tff(v.x); v.y = f2tff(v.y); v.z = f2tff(v.z); v.w = f2tff(v.w);
            *(float4*)&Xs[row * PLD + c4 * 4] = v;
        }
        // W tile transposed: Ws[c][o], tf32-converted
#pragma unroll
        for (int t = 0; t < 4; t++) {
            int lin = tid + t * 256;
            int o   = lin >> 3;
            int kc4 = lin & 7;
            float4 v = *(const float4*)&w[(size_t)o * CIN + c0 + kc4 * 4];
            Ws[(kc4 * 4 + 0) * PLD + o] = f2tff(v.x);
            Ws[(kc4 * 4 + 1) * PLD + o] = f2tff(v.y);
            Ws[(kc4 * 4 + 2) * PLD + o] = f2tff(v.z);
            Ws[(kc4 * 4 + 3) * PLD + o] = f2tff(v.w);
        }
        __syncthreads();

#pragma unroll
        for (int ks = 0; ks < 4; ks++) {
            int kc = ks * 8;
            // A fragments: rows pb+16*mt+{g,g+8}, cols kc+{t4,t4+4}
            uint32_t a[2][4];
#pragma unroll
            for (int mt = 0; mt < 2; mt++) {
                int pr = pb + 16 * mt;
                a[mt][0] = U(Xs[(kc + t4) * PLD + pr + g]);
                a[mt][1] = U(Xs[(kc + t4) * PLD + pr + g + 8]);
                a[mt][2] = U(Xs[(kc + t4 + 4) * PLD + pr + g]);
                a[mt][3] = U(Xs[(kc + t4 + 4) * PLD + pr + g + 8]);
            }
#pragma unroll
            for (int nt = 0; nt < 8; nt++) {
                uint32_t b0 = U(Ws[(kc + t4) * PLD + ob + nt * 8 + g]);
                uint32_t b1 = U(Ws[(kc + t4 + 4) * PLD + ob + nt * 8 + g]);
                mma_tf32(acc[0][nt], a[0][0], a[0][1], a[0][2], a[0][3], b0, b1);
                mma_tf32(acc[1][nt], a[1][0], a[1][1], a[1][2], a[1][3], b0, b1);
            }
        }
    }

    // epilogue: BN + ReLU -> staging (overlay) -> coalesced f4 store
    __syncthreads();
    float* Fs = psm;   // [128][PLD]
#pragma unroll
    for (int mt = 0; mt < 2; mt++) {
#pragma unroll
        for (int nt = 0; nt < 8; nt++) {
            int c  = ob + nt * 8 + 2 * t4;
            float s0 = gamma[c]     * rsqrtf(var[c]     + EPSBN);
            float s1 = gamma[c + 1] * rsqrtf(var[c + 1] + EPSBN);
            float h0 = beta[c]     - mean[c]     * s0;
            float h1 = beta[c + 1] - mean[c + 1] * s1;
            int r = pb + 16 * mt + g;
            float2 v0, v1;
            v0.x = fmaxf(fmaf(acc[mt][nt][0], s0, h0), 0.f);
            v0.y = fmaxf(fmaf(acc[mt][nt][1], s1, h1), 0.f);
            v1.x = fmaxf(fmaf(acc[mt][nt][2], s0, h0), 0.f);
            v1.y = fmaxf(fmaf(acc[mt][nt][3], s1, h1), 0.f);
            *(float2*)&Fs[r * PLD + c]       = v0;
            *(float2*)&Fs[(r + 8) * PLD + c] = v1;
        }
    }
    __syncthreads();
#pragma unroll
    for (int t = 0; t < 16; t++) {
        int lin = tid + t * 256;
        int row = lin >> 5;
        int c4  = lin & 31;
        float4 v = *(const float4*)&Fs[row * PLD + c4 * 4];
        *(float4*)&out[((size_t)bb * HWP + p0 + row) * CO + c4 * 4] = v;
    }
}

// ---------------------------------------------------------------------------
// Flash attention, tf32 MMA. TQ=64, TK=64, D=128. 128 threads (4 warps),
// warp owns 16 q rows. grid (CHUNKP/64, NCHUNK, B).
// ---------------------------------------------------------------------------
#define QK_LD 132
#define PS_LD 68
#define ATTN_SMEM ((2 * 64 * QK_LD + 64 * PS_LD) * 4)

__global__ __launch_bounds__(128)
void attn_kernel(const float* __restrict__ imgp,  // [B][HWP][CO]
                 const float* __restrict__ lidp,  // [B][HWP][CO]
                 const float* __restrict__ mw,
                 float* __restrict__ out)         // [B][CO][HWP]
{
    extern __shared__ float sm[];
    float* Qs = sm;                      // [64][QK_LD]  scaled tf32 Q
    float* Ks = sm + 64 * QK_LD;         // [64][QK_LD]  tf32 K
    float* Ps = sm + 2 * 64 * QK_LD;     // [64][PS_LD]  tf32 P

    const int tid  = threadIdx.x;
    const int wid  = tid >> 5;
    const int lane = tid & 31;
    const int g    = lane >> 2;
    const int t4   = lane & 3;
    const int qb   = wid * 16;
    const int chunk = blockIdx.y;
    const int bb    = blockIdx.z;
    const int pq0   = chunk * CHUNKP + blockIdx.x * 64;

    // Q tile: pre-scaled by 1/sqrt(C), tf32
#pragma unroll
    for (int t = 0; t < 16; t++) {
        int lin = tid + t * 128;
        int row = lin >> 5;
        int c4  = lin & 31;
        float4 v = *(const float4*)&imgp[((size_t)bb * HWP + pq0 + row) * CO + c4 * 4];
        v.x = f2tff(v.x * SCALE); v.y = f2tff(v.y * SCALE);
        v.z = f2tff(v.z * SCALE); v.w = f2tff(v.w * SCALE);
        *(float4*)&Qs[row * QK_LD + c4 * 4] = v;
    }

    float oacc[16][4];
#pragma unroll
    for (int nt = 0; nt < 16; nt++)
#pragma unroll
        for (int i = 0; i < 4; i++) oacc[nt][i] = 0.f;
    float m0 = -1e30f, m1 = -1e30f, l0 = 0.f, l1 = 0.f;

    for (int kt = 0; kt < CHUNKP / 64; kt++) {
        __syncthreads();
        const int pk0 = chunk * CHUNKP + kt * 64;
#pragma unroll
        for (int t = 0; t < 16; t++) {
            int lin = tid + t * 128;
            int row = lin >> 5;
            int c4  = lin & 31;
            float4 v = *(const float4*)&lidp[((size_t)bb * HWP + pk0 + row) * CO + c4 * 4];
            v.x = f2tff(v.x); v.y = f2tff(v.y); v.z = f2tff(v.z); v.w = f2tff(v.w);
            *(float4*)&Ks[row * QK_LD + c4 * 4] = v;
        }
        __syncthreads();

        // ---- S = Q . K^T : warp computes rows [qb,qb+16) x 64 cols ----
        float sc[8][4];
#pragma unroll
        for (int nt = 0; nt < 8; nt++)
#pragma unroll
            for (int i = 0; i < 4; i++) sc[nt][i] = 0.f;

#pragma unroll
        for (int ks = 0; ks < 16; ks++) {
            int kc = ks * 8;
            uint32_t a0 = U(Qs[(qb + g) * QK_LD + kc + t4]);
            uint32_t a1 = U(Qs[(qb + g + 8) * QK_LD + kc + t4]);
            uint32_t a2 = U(Qs[(qb + g) * QK_LD + kc + t4 + 4]);
            uint32_t a3 = U(Qs[(qb + g + 8) * QK_LD + kc + t4 + 4]);
#pragma unroll
            for (int nt = 0; nt < 8; nt++) {
                uint32_t b0 = U(Ks[(nt * 8 + g) * QK_LD + kc + t4]);
                uint32_t b1 = U(Ks[(nt * 8 + g) * QK_LD + kc + t4 + 4]);
                mma_tf32(sc[nt], a0, a1, a2, a3, b0, b1);
            }
        }

        // ---- online softmax (rows qb+g and qb+g+8; reduce over 4 t-lanes) ----
        float mx0 = -1e30f, mx1 = -1e30f;
#pragma unroll
        for (int nt = 0; nt < 8; nt++) {
            mx0 = fmaxf(mx0, fmaxf(sc[nt][0], sc[nt][1]));
            mx1 = fmaxf(mx1, fmaxf(sc[nt][2], sc[nt][3]));
        }
        mx0 = fmaxf(mx0, __shfl_xor_sync(0xffffffffu, mx0, 1));
        mx0 = fmaxf(mx0, __shfl_xor_sync(0xffffffffu, mx0, 2));
        mx1 = fmaxf(mx1, __shfl_xor_sync(0xffffffffu, mx1, 1));
        mx1 = fmaxf(mx1, __shfl_xor_sync(0xffffffffu, mx1, 2));
        float mn0 = fmaxf(m0, mx0), mn1 = fmaxf(m1, mx1);
        float cr0 = __expf(m0 - mn0), cr1 = __expf(m1 - mn1);
        m0 = mn0; m1 = mn1;
        float ps0 = 0.f, ps1 = 0.f;
#pragma unroll
        for (int nt = 0; nt < 8; nt++) {
            float p00 = __expf(sc[nt][0] - mn0);
            float p01 = __expf(sc[nt][1] - mn0);
            float p10 = __expf(sc[nt][2] - mn1);
            float p11 = __expf(sc[nt][3] - mn1);
            ps0 += p00 + p01; ps1 += p10 + p11;
            float2 v0 = make_float2(f2tff(p00), f2tff(p01));
            float2 v1 = make_float2(f2tff(p10), f2tff(p11));
            *(float2*)&Ps[(qb + g) * PS_LD + nt * 8 + 2 * t4]     = v0;
            *(float2*)&Ps[(qb + g + 8) * PS_LD + nt * 8 + 2 * t4] = v1;
        }
        ps0 += __shfl_xor_sync(0xffffffffu, ps0, 1);
        ps0 += __shfl_xor_sync(0xffffffffu, ps0, 2);
        ps1 += __shfl_xor_sync(0xffffffffu, ps1, 1);
        ps1 += __shfl_xor_sync(0xffffffffu, ps1, 2);
        l0 = l0 * cr0 + ps0;
        l1 = l1 * cr1 + ps1;
#pragma unroll
        for (int nt = 0; nt < 16; nt++) {
            oacc[nt][0] *= cr0; oacc[nt][1] *= cr0;
            oacc[nt][2] *= cr1; oacc[nt][3] *= cr1;
        }
        __syncthreads();

        // ---- O += P . K : rows [qb,qb+16) x 128 d-cols ----
#pragma unroll
        for (int ks = 0; ks < 8; ks++) {
            int kc = ks * 8;
            uint32_t a0 = U(Ps[(qb + g) * PS_LD + kc + t4]);
            uint32_t a1 = U(Ps[(qb + g + 8) * PS_LD + kc + t4]);
            uint32_t a2 = U(Ps[(qb + g) * PS_LD + kc + t4 + 4]);
            uint32_t a3 = U(Ps[(qb + g + 8) * PS_LD + kc + t4 + 4]);
#pragma unroll
            for (int nt = 0; nt < 16; nt++) {
                uint32_t b0 = U(Ks[(kc + t4) * QK_LD + nt * 8 + g]);
                uint32_t b1 = U(Ks[(kc + t4 + 4) * QK_LD + nt * 8 + g]);
                mma_tf32(oacc[nt], a0, a1, a2, a3, b0, b1);
            }
        }
    }

    // ---- blend epilogue: fused = O/l; out = w0*image + w1*fused ----
    float e0 = __expf(mw[0]), e1 = __expf(mw[1]);
    float w0 = e0 / (e0 + e1), w1 = e1 / (e0 + e1);
    float il0 = 1.f / l0, il1 = 1.f / l1;
    const float* imb0 = imgp + ((size_t)bb * HWP + pq0 + qb + g) * CO;
    const float* imb1 = imb0 + 8 * CO;
#pragma unroll
    for (int nt = 0; nt < 16; nt++) {
        int c = nt * 8 + 2 * t4;
        float2 i0 = *(const float2*)&imb0[c];
        float2 i1 = *(const float2*)&imb1[c];
        float2 v0, v1;
        v0.x = w0 * i0.x + w1 * oacc[nt][0] * il0;
        v0.y = w0 * i0.y + w1 * oacc[nt][1] * il0;
        v1.x = w0 * i1.x + w1 * oacc[nt][2] * il1;
        v1.y = w0 * i1.y + w1 * oacc[nt][3] * il1;
        *(float2*)&Qs[(qb + g) * QK_LD + c]     = v0;   // Qs reused as staging
        *(float2*)&Qs[(qb + g + 8) * QK_LD + c] = v1;
    }
    __syncthreads();

    float* ob = out + (size_t)bb * CO * HWP;
#pragma unroll
    for (int t = 0; t < 64; t++) {
        int lin = tid + t * 128;
        int c   = lin >> 6;
        int pi  = lin & 63;
        ob[(size_t)c * HWP + pq0 + pi] = Qs[pi * QK_LD + c];
    }
}

// ---------------------------------------------------------------------------
extern "C" void kernel_launch(void* const* d_in, const int* in_sizes, int n_in,
                              void* d_out, int out_size)
{
    const float* lidar_x = (const float*)d_in[0];
    const float* image_x = (const float*)d_in[1];
    const float* lw  = (const float*)d_in[2];
    const float* lg  = (const float*)d_in[3];
    const float* lb  = (const float*)d_in[4];
    const float* lm  = (const float*)d_in[5];
    const float* lv  = (const float*)d_in[6];
    const float* iw  = (const float*)d_in[7];
    const float* ig  = (const float*)d_in[8];
    const float* ib  = (const float*)d_in[9];
    const float* im  = (const float*)d_in[10];
    const float* iv  = (const float*)d_in[11];
    const float* mw  = (const float*)d_in[12];
    float* out = (float*)d_out;

    float *lp = nullptr, *ip = nullptr;
    cudaGetSymbolAddress((void**)&lp, g_lidar_proj);
    cudaGetSymbolAddress((void**)&ip, g_image_proj);
    cudaFuncSetAttribute(proj_kernel<CLI>, cudaFuncAttributeMaxDynamicSharedMemorySize, PROJ_SMEM);
    cudaFuncSetAttribute(proj_kernel<CIM>, cudaFuncAttributeMaxDynamicSharedMemorySize, PROJ_SMEM);
    cudaFuncSetAttribute(attn_kernel, cudaFuncAttributeMaxDynamicSharedMemorySize, ATTN_SMEM);

    dim3 pgrid(HWP / 128, BB);
    proj_kernel<CLI><<<pgrid, 256, PROJ_SMEM>>>(lidar_x, lw, lg, lb, lm, lv, lp);
    proj_kernel<CIM><<<pgrid, 256, PROJ_SMEM>>>(image_x, iw, ig, ib, im, iv, ip);

    dim3 agrid(CHUNKP / 64, NCHUNK, BB);
    attn_kernel<<<agrid, 128, ATTN_SMEM>>>(ip, lp, mw, out);
}

// round 5
// speedup vs baseline: 4.9811x; 1.8060x over previous
#include <cuda_runtime.h>
#include <cuda_fp16.h>
#include <math.h>
#include <stdint.h>

#define BB     2
#define HWP    16384
#define CO     128
#define CLI    256
#define CIM    512
#define CHUNKP 2048
#define NCHUNK 8
#define EPSBN  1e-5f
#define SCALE  0.08838834764831845f   // 1/sqrt(128)

__device__ float g_lidar_proj[BB * HWP * CO];
__device__ float g_image_proj[BB * HWP * CO];

// ------------------------- tf32 helpers (proj) -----------------------------
__device__ __forceinline__ uint32_t f2tf(float x) {
    uint32_t u; asm("cvt.rna.tf32.f32 %0, %1;" : "=r"(u) : "f"(x)); return u;
}
__device__ __forceinline__ float f2tff(float x) { return __uint_as_float(f2tf(x)); }
__device__ __forceinline__ void mma_tf32(float* c, uint32_t a0, uint32_t a1,
                                         uint32_t a2, uint32_t a3, uint32_t b0, uint32_t b1) {
    asm volatile("mma.sync.aligned.m16n8k8.row.col.f32.tf32.tf32.f32 "
                 "{%0,%1,%2,%3}, {%4,%5,%6,%7}, {%8,%9}, {%0,%1,%2,%3};"
                 : "+f"(c[0]), "+f"(c[1]), "+f"(c[2]), "+f"(c[3])
                 : "r"(a0), "r"(a1), "r"(a2), "r"(a3), "r"(b0), "r"(b1));
}
#define U(x) __float_as_uint(x)

// ------------------------- fp16 helpers (attention) ------------------------
__device__ __forceinline__ uint32_t smem_u32(const void* p) {
    uint32_t a;
    asm("{ .reg .u64 t; cvta.to.shared.u64 t, %1; cvt.u32.u64 %0, t; }" : "=r"(a) : "l"(p));
    return a;
}
__device__ __forceinline__ void mma16816(float* c, const uint32_t* a, const uint32_t* b) {
    asm volatile("mma.sync.aligned.m16n8k16.row.col.f32.f16.f16.f32 "
                 "{%0,%1,%2,%3}, {%4,%5,%6,%7}, {%8,%9}, {%0,%1,%2,%3};"
                 : "+f"(c[0]), "+f"(c[1]), "+f"(c[2]), "+f"(c[3])
                 : "r"(a[0]), "r"(a[1]), "r"(a[2]), "r"(a[3]), "r"(b[0]), "r"(b[1]));
}
__device__ __forceinline__ void ldsm_x4(uint32_t* r, uint32_t a) {
    asm volatile("ldmatrix.sync.aligned.m8n8.x4.shared.b16 {%0,%1,%2,%3}, [%4];"
                 : "=r"(r[0]), "=r"(r[1]), "=r"(r[2]), "=r"(r[3]) : "r"(a));
}
__device__ __forceinline__ void ldsm_x2(uint32_t* r, uint32_t a) {
    asm volatile("ldmatrix.sync.aligned.m8n8.x2.shared.b16 {%0,%1}, [%2];"
                 : "=r"(r[0]), "=r"(r[1]) : "r"(a));
}
__device__ __forceinline__ void ldsm_x2t(uint32_t* r, uint32_t a) {
    asm volatile("ldmatrix.sync.aligned.m8n8.x2.trans.shared.b16 {%0,%1}, [%2];"
                 : "=r"(r[0]), "=r"(r[1]) : "r"(a));
}

// ------------------------- projection (unchanged, known-good) --------------
#define PLD 132
#define PROJ_SMEM (128 * PLD * 4)
template<int CIN>
__global__ __launch_bounds__(256)
void proj_kernel(const float* __restrict__ x, const float* __restrict__ w,
                 const float* __restrict__ gamma, const float* __restrict__ beta,
                 const float* __restrict__ mean, const float* __restrict__ var,
                 float* __restrict__ out)
{
    extern __shared__ float psm[];
    float* Xs = psm;
    float* Ws = psm + 32 * PLD;
    const int tid = threadIdx.x, wid = tid >> 5, lane = tid & 31;
    const int g = lane >> 2, t4 = lane & 3;
    const int pb = (wid >> 1) * 32, ob = (wid & 1) * 64;
    const int bb = blockIdx.y, p0 = blockIdx.x * 128;
    float acc[2][8][4];
#pragma unroll
    for (int mt = 0; mt < 2; mt++)
#pragma unroll
        for (int nt = 0; nt < 8; nt++)
#pragma unroll
            for (int i = 0; i < 4; i++) acc[mt][nt][i] = 0.f;
    const float* xb = x + (size_t)bb * CIN * HWP;
    for (int c0 = 0; c0 < CIN; c0 += 32) {
        __syncthreads();
#pragma unroll
        for (int t = 0; t < 4; t++) {
            int lin = tid + t * 256, row = lin >> 5, c4 = lin & 31;
            float4 v = *(const float4*)&xb[(size_t)(c0 + row) * HWP + p0 + c4 * 4];
            v.x = f2tff(v.x); v.y = f2tff(v.y); v.z = f2tff(v.z); v.w = f2tff(v.w);
            *(float4*)&Xs[row * PLD + c4 * 4] = v;
        }
#pragma unroll
        for (int t = 0; t < 4; t++) {
            int lin = tid + t * 256, o = lin >> 3, kc4 = lin & 7;
            float4 v = *(const float4*)&w[(size_t)o * CIN + c0 + kc4 * 4];
            Ws[(kc4 * 4 + 0) * PLD + o] = f2tff(v.x);
            Ws[(kc4 * 4 + 1) * PLD + o] = f2tff(v.y);
            Ws[(kc4 * 4 + 2) * PLD + o] = f2tff(v.z);
            Ws[(kc4 * 4 + 3) * PLD + o] = f2tff(v.w);
        }
        __syncthreads();
#pragma unroll
        for (int ks = 0; ks < 4; ks++) {
            int kc = ks * 8;
            uint32_t a[2][4];
#pragma unroll
            for (int mt = 0; mt < 2; mt++) {
                int pr = pb + 16 * mt;
                a[mt][0] = U(Xs[(kc + t4) * PLD + pr + g]);
                a[mt][1] = U(Xs[(kc + t4) * PLD + pr + g + 8]);
                a[mt][2] = U(Xs[(kc + t4 + 4) * PLD + pr + g]);
                a[mt][3] = U(Xs[(kc + t4 + 4) * PLD + pr + g + 8]);
            }
#pragma unroll
            for (int nt = 0; nt < 8; nt++) {
                uint32_t b0 = U(Ws[(kc + t4) * PLD + ob + nt * 8 + g]);
                uint32_t b1 = U(Ws[(kc + t4 + 4) * PLD + ob + nt * 8 + g]);
                mma_tf32(acc[0][nt], a[0][0], a[0][1], a[0][2], a[0][3], b0, b1);
                mma_tf32(acc[1][nt], a[1][0], a[1][1], a[1][2], a[1][3], b0, b1);
            }
        }
    }
    __syncthreads();
    float* Fs = psm;
#pragma unroll
    for (int mt = 0; mt < 2; mt++)
#pragma unroll
        for (int nt = 0; nt < 8; nt++) {
            int c = ob + nt * 8 + 2 * t4;
            float s0 = gamma[c] * rsqrtf(var[c] + EPSBN);
            float s1 = gamma[c + 1] * rsqrtf(var[c + 1] + EPSBN);
            float h0 = beta[c] - mean[c] * s0, h1 = beta[c + 1] - mean[c + 1] * s1;
            int r = pb + 16 * mt + g;
            float2 v0, v1;
            v0.x = fmaxf(fmaf(acc[mt][nt][0], s0, h0), 0.f);
            v0.y = fmaxf(fmaf(acc[mt][nt][1], s1, h1), 0.f);
            v1.x = fmaxf(fmaf(acc[mt][nt][2], s0, h0), 0.f);
            v1.y = fmaxf(fmaf(acc[mt][nt][3], s1, h1), 0.f);
            *(float2*)&Fs[r * PLD + c] = v0;
            *(float2*)&Fs[(r + 8) * PLD + c] = v1;
        }
    __syncthreads();
#pragma unroll
    for (int t = 0; t < 16; t++) {
        int lin = tid + t * 256, row = lin >> 5, c4 = lin & 31;
        *(float4*)&out[((size_t)bb * HWP + p0 + row) * CO + c4 * 4] = *(float4*)&Fs[row * PLD + c4 * 4];
    }
}

// --------------------- fp16 warp-specialized flash attention ---------------
// TQ=128, TK=64, D=128. 384 threads: warps 0-3 = S (m32xn64 each),
// warps 4-11 = O (m32 x d64 each). grid (16, 8, 2).
// smem bytes: cr[2]@0,512  l@1024  Q@2048 (128x136h)  K@36864 (4 x 64x136h)
//             P@106496 (2 x 128x72h).  Epilogue staging overlays K region.
#define NIT   32
#define CR0B  0
#define CR1B  512
#define LBB   1024
#define QB    2048
#define KB    36864
#define KBUFB 17408
#define PB    106496
#define PBUFB 18432
#define ATTN_SMEM 143360
#define QLDB  272       // 136 halfs
#define PLDB  144       // 72 halfs

__device__ __forceinline__ void fill_k(char* smc, const float* kb, int buf, int tid) {
    char* kd = smc + KB + buf * KBUFB;
#pragma unroll
    for (int t = 0; t < 6; t++) {
        int lin = tid + t * 384;
        if (lin < 2048) {
            int row = lin >> 5, c4 = lin & 31;
            float4 v = *(const float4*)&kb[(size_t)row * CO + c4 * 4];
            __half2 h0 = __floats2half2_rn(v.x, v.y);
            __half2 h1 = __floats2half2_rn(v.z, v.w);
            uint2 u; u.x = *(uint32_t*)&h0; u.y = *(uint32_t*)&h1;
            *(uint2*)(kd + row * QLDB + c4 * 8) = u;
        }
    }
}

__global__ __launch_bounds__(384)
void attn_kernel(const float* __restrict__ imgp, const float* __restrict__ lidp,
                 const float* __restrict__ mw, float* __restrict__ out)
{
    extern __shared__ char smc[];
    const uint32_t sbu = smem_u32(smc);
    float* crb[2] = { (float*)(smc + CR0B), (float*)(smc + CR1B) };
    float* lbuf   = (float*)(smc + LBB);
    const int tid = threadIdx.x, wid = tid >> 5, lane = tid & 31;
    const int g = lane >> 2, t4 = lane & 3;
    const int l15 = lane & 15, l7 = lane & 7;
    const int chunk = blockIdx.y, bb = blockIdx.z;
    const int pq0 = chunk * CHUNKP + blockIdx.x * 128;

    // ---- load Q (scaled fp16) ----
    const float* imb = imgp + ((size_t)bb * HWP + pq0) * CO;
#pragma unroll
    for (int t = 0; t < 11; t++) {
        int lin = tid + t * 384;
        if (lin < 4096) {
            int row = lin >> 5, c4 = lin & 31;
            float4 v = *(const float4*)&imb[(size_t)row * CO + c4 * 4];
            __half2 h0 = __floats2half2_rn(v.x * SCALE, v.y * SCALE);
            __half2 h1 = __floats2half2_rn(v.z * SCALE, v.w * SCALE);
            uint2 u; u.x = *(uint32_t*)&h0; u.y = *(uint32_t*)&h1;
            *(uint2*)(smc + QB + row * QLDB + c4 * 8) = u;
        }
    }
    const float* ldb = lidp + ((size_t)bb * HWP + chunk * CHUNKP) * CO;
    fill_k(smc, ldb, 0, tid);

    float acc[2][8][4];   // S-warps: scores (per iter); O-warps: O accumulator
#pragma unroll
    for (int mt = 0; mt < 2; mt++)
#pragma unroll
        for (int nt = 0; nt < 8; nt++)
#pragma unroll
            for (int r = 0; r < 4; r++) acc[mt][nt][r] = 0.f;
    float mrow[4] = {-3.0e38f, -3.0e38f, -3.0e38f, -3.0e38f};
    float lrow[4] = {0.f, 0.f, 0.f, 0.f};

    const int s_mb = (wid & 3) * 32;          // S-warp row base
    const int o_mb = ((wid - 4) & 3) * 32;    // O-warp row base
    const int o_db = ((wid - 4) >> 2) * 64;   // O-warp d base

    for (int i = 0; i < NIT; i++) {
        if (i + 1 < NIT) fill_k(smc, ldb + (size_t)(i + 1) * 64 * CO, (i + 1) & 3, tid);
        __syncthreads();

        if (wid < 4) {
            // ================= S-warps: S(i) = Q K^T, softmax, P, cr =======
            const uint32_t kbase = sbu + KB + (uint32_t)(i & 3) * KBUFB;
            const uint32_t qbase = sbu + QB;
#pragma unroll
            for (int mt = 0; mt < 2; mt++)
#pragma unroll
                for (int nt = 0; nt < 8; nt++)
#pragma unroll
                    for (int r = 0; r < 4; r++) acc[mt][nt][r] = 0.f;
#pragma unroll
            for (int ks = 0; ks < 8; ks++) {
                int kc = ks * 16;
                uint32_t qa0[4], qa1[4];
                int acol = kc + ((lane >> 4) << 3);
                ldsm_x4(qa0, qbase + (s_mb + l15) * QLDB + acol * 2);
                ldsm_x4(qa1, qbase + (s_mb + 16 + l15) * QLDB + acol * 2);
                int bcol = kc + (((lane >> 3) & 1) << 3);
#pragma unroll
                for (int nt = 0; nt < 8; nt++) {
                    uint32_t b[2];
                    ldsm_x2(b, kbase + (nt * 8 + l7) * QLDB + bcol * 2);
                    mma16816(acc[0][nt], qa0, b);
                    mma16816(acc[1][nt], qa1, b);
                }
            }
            // softmax: 4 row-states, row = s_mb + 16*mt + 8*h + g
            char* pdst = smc + PB + (i & 1) * PBUFB;
            float* crw = crb[i & 1];
#pragma unroll
            for (int mt = 0; mt < 2; mt++)
#pragma unroll
                for (int h = 0; h < 2; h++) {
                    int s = 2 * mt + h;
                    int row = s_mb + 16 * mt + 8 * h + g;
                    float rm = -3.0e38f;
#pragma unroll
                    for (int nt = 0; nt < 8; nt++)
                        rm = fmaxf(rm, fmaxf(acc[mt][nt][2 * h], acc[mt][nt][2 * h + 1]));
                    rm = fmaxf(rm, __shfl_xor_sync(0xffffffffu, rm, 1));
                    rm = fmaxf(rm, __shfl_xor_sync(0xffffffffu, rm, 2));
                    float mn = fmaxf(mrow[s], rm);
                    float cr = __expf(mrow[s] - mn);
                    mrow[s] = mn;
                    float ps = 0.f;
#pragma unroll
                    for (int nt = 0; nt < 8; nt++) {
                        float p0 = __expf(acc[mt][nt][2 * h] - mn);
                        float p1 = __expf(acc[mt][nt][2 * h + 1] - mn);
                        ps += p0 + p1;
                        __half2 hp = __floats2half2_rn(p0, p1);
                        *(uint32_t*)(pdst + row * PLDB + (nt * 8 + 2 * t4) * 2) = *(uint32_t*)&hp;
                    }
                    ps += __shfl_xor_sync(0xffffffffu, ps, 1);
                    ps += __shfl_xor_sync(0xffffffffu, ps, 2);
                    lrow[s] = lrow[s] * cr + ps;
                    if (t4 == 0) crw[row] = cr;
                }
        } else if (i > 0) {
            // ================= O-warps: O = O*cr(i-1) + P(i-1) K(i-1) ======
            const int j = i - 1;
            const float* crr = crb[j & 1];
            float crv[4];
#pragma unroll
            for (int s = 0; s < 4; s++)
                crv[s] = crr[o_mb + 16 * (s >> 1) + 8 * (s & 1) + g];
#pragma unroll
            for (int mt = 0; mt < 2; mt++)
#pragma unroll
                for (int nt = 0; nt < 8; nt++)
#pragma unroll
                    for (int h = 0; h < 2; h++) {
                        acc[mt][nt][2 * h]     *= crv[2 * mt + h];
                        acc[mt][nt][2 * h + 1] *= crv[2 * mt + h];
                    }
            const uint32_t pbase = sbu + PB + (uint32_t)(j & 1) * PBUFB;
            const uint32_t kbase = sbu + KB + (uint32_t)(j & 3) * KBUFB;
#pragma unroll
            for (int kq = 0; kq < 4; kq++) {
                int kbv = kq * 16;
                uint32_t pa0[4], pa1[4];
                int acol = kbv + ((lane >> 4) << 3);
                ldsm_x4(pa0, pbase + (o_mb + l15) * PLDB + acol * 2);
                ldsm_x4(pa1, pbase + (o_mb + 16 + l15) * PLDB + acol * 2);
#pragma unroll
                for (int nt = 0; nt < 8; nt++) {
                    uint32_t b[2];
                    ldsm_x2t(b, kbase + (kbv + l15) * QLDB + (o_db + nt * 8) * 2);
                    mma16816(acc[0][nt], pa0, b);
                    mma16816(acc[1][nt], pa1, b);
                }
            }
        }
    }

    // ---- final: l to smem, last O update, blend ----
    if (wid < 4) {
        if (t4 == 0) {
#pragma unroll
            for (int s = 0; s < 4; s++)
                lbuf[s_mb + 16 * (s >> 1) + 8 * (s & 1) + g] = lrow[s];
        }
    }
    __syncthreads();

    float e0 = __expf(mw[0]), e1 = __expf(mw[1]);
    float w0 = e0 / (e0 + e1), w1 = e1 / (e0 + e1);
    float* fs2 = (float*)(smc + KB);   // staging [128 c][136 p] overlays K

    if (wid >= 4) {
        // last O update (tile NIT-1)
        const int j = NIT - 1;
        const float* crr = crb[j & 1];
        float crv[4];
#pragma unroll
        for (int s = 0; s < 4; s++)
            crv[s] = crr[o_mb + 16 * (s >> 1) + 8 * (s & 1) + g];
#pragma unroll
        for (int mt = 0; mt < 2; mt++)
#pragma unroll
            for (int nt = 0; nt < 8; nt++)
#pragma unroll
                for (int h = 0; h < 2; h++) {
                    acc[mt][nt][2 * h]     *= crv[2 * mt + h];
                    acc[mt][nt][2 * h + 1] *= crv[2 * mt + h];
                }
        const uint32_t pbase = sbu + PB + (uint32_t)(j & 1) * PBUFB;
        const uint32_t kbase = sbu + KB + (uint32_t)(j & 3) * KBUFB;
#pragma unroll
        for (int kq = 0; kq < 4; kq++) {
            int kbv = kq * 16;
            uint32_t pa0[4], pa1[4];
            int acol = kbv + ((lane >> 4) << 3);
            ldsm_x4(pa0, pbase + (o_mb + l15) * PLDB + acol * 2);
            ldsm_x4(pa1, pbase + (o_mb + 16 + l15) * PLDB + acol * 2);
#pragma unroll
            for (int nt = 0; nt < 8; nt++) {
                uint32_t b[2];
                ldsm_x2t(b, kbase + (kbv + l15) * QLDB + (o_db + nt * 8) * 2);
                mma16816(acc[0][nt], pa0, b);
                mma16816(acc[1][nt], pa1, b);
            }
        }
        // blend: fused = w0*img + w1*O/l, staged transposed [c][p]
        float il[4];
#pragma unroll
        for (int s = 0; s < 4; s++)
            il[s] = 1.f / lbuf[o_mb + 16 * (s >> 1) + 8 * (s & 1) + g];
#pragma unroll
        for (int mt = 0; mt < 2; mt++)
#pragma unroll
            for (int h = 0; h < 2; h++) {
                int row = o_mb + 16 * mt + 8 * h + g;
                float sc = il[2 * mt + h];
                const float* ir = imgp + ((size_t)bb * HWP + pq0 + row) * CO;
#pragma unroll
                for (int nt = 0; nt < 8; nt++) {
                    int c = o_db + nt * 8 + 2 * t4;
                    float2 iv = *(const float2*)&ir[c];
                    fs2[(c) * 136 + row]     = w0 * iv.x + w1 * acc[mt][nt][2 * h] * sc;
                    fs2[(c + 1) * 136 + row] = w0 * iv.y + w1 * acc[mt][nt][2 * h + 1] * sc;
                }
            }
    }
    __syncthreads();

    // coalesced writeout: out[b][c][pq0 + p]
    float* ob = out + (size_t)bb * CO * HWP;
#pragma unroll
    for (int t = 0; t < 11; t++) {
        int lin = tid + t * 384;
        if (lin < 4096) {
            int c = lin >> 5, p4 = lin & 31;
            float4 v = *(const float4*)&fs2[c * 136 + p4 * 4];
            *(float4*)&ob[(size_t)c * HWP + pq0 + p4 * 4] = v;
        }
    }
}

// ---------------------------------------------------------------------------
extern "C" void kernel_launch(void* const* d_in, const int* in_sizes, int n_in,
                              void* d_out, int out_size)
{
    const float* lidar_x = (const float*)d_in[0];
    const float* image_x = (const float*)d_in[1];
    const float* lw = (const float*)d_in[2];
    const float* lg = (const float*)d_in[3];
    const float* lb = (const float*)d_in[4];
    const float* lm = (const float*)d_in[5];
    const float* lv = (const float*)d_in[6];
    const float* iw = (const float*)d_in[7];
    const float* ig = (const float*)d_in[8];
    const float* ib = (const float*)d_in[9];
    const float* im = (const float*)d_in[10];
    const float* iv = (const float*)d_in[11];
    const float* mw = (const float*)d_in[12];
    float* out = (float*)d_out;

    float *lp = nullptr, *ip = nullptr;
    cudaGetSymbolAddress((void**)&lp, g_lidar_proj);
    cudaGetSymbolAddress((void**)&ip, g_image_proj);
    cudaFuncSetAttribute(proj_kernel<CLI>, cudaFuncAttributeMaxDynamicSharedMemorySize, PROJ_SMEM);
    cudaFuncSetAttribute(proj_kernel<CIM>, cudaFuncAttributeMaxDynamicSharedMemorySize, PROJ_SMEM);
    cudaFuncSetAttribute(attn_kernel, cudaFuncAttributeMaxDynamicSharedMemorySize, ATTN_SMEM);

    dim3 pgrid(HWP / 128, BB);
    proj_kernel<CLI><<<pgrid, 256, PROJ_SMEM>>>(lidar_x, lw, lg, lb, lm, lv, lp);
    proj_kernel<CIM><<<pgrid, 256, PROJ_SMEM>>>(image_x, iw, ig, ib, im, iv, ip);

    dim3 agrid(CHUNKP / 128, NCHUNK, BB);
    attn_kernel<<<agrid, 384, ATTN_SMEM>>>(ip, lp, mw, out);
}

// round 6
// speedup vs baseline: 5.2033x; 1.0446x over previous
#include <cuda_runtime.h>
#include <cuda_fp16.h>
#include <math.h>
#include <stdint.h>

#define BB     2
#define HWP    16384
#define CO     128
#define CLI    256
#define CIM    512
#define CHUNKP 2048
#define NCHUNK 8
#define EPSBN  1e-5f
#define SCALE  0.08838834764831845f   // 1/sqrt(128)

// Scratch: fp16 operand copies (q pre-scaled), fp32 image for blend
__device__ __half g_q16[BB * HWP * CO];
__device__ __half g_k16[BB * HWP * CO];
__device__ float  g_image_proj[BB * HWP * CO];

// ------------------------------ helpers ------------------------------------
__device__ __forceinline__ uint32_t smem_u32(const void* p) {
    uint32_t a;
    asm("{ .reg .u64 t; cvta.to.shared.u64 t, %1; cvt.u32.u64 %0, t; }" : "=r"(a) : "l"(p));
    return a;
}
__device__ __forceinline__ void mma16816(float* c, const uint32_t* a, const uint32_t* b) {
    asm volatile("mma.sync.aligned.m16n8k16.row.col.f32.f16.f16.f32 "
                 "{%0,%1,%2,%3}, {%4,%5,%6,%7}, {%8,%9}, {%0,%1,%2,%3};"
                 : "+f"(c[0]), "+f"(c[1]), "+f"(c[2]), "+f"(c[3])
                 : "r"(a[0]), "r"(a[1]), "r"(a[2]), "r"(a[3]), "r"(b[0]), "r"(b[1]));
}
__device__ __forceinline__ void ldsm_x4(uint32_t* r, uint32_t a) {
    asm volatile("ldmatrix.sync.aligned.m8n8.x4.shared.b16 {%0,%1,%2,%3}, [%4];"
                 : "=r"(r[0]), "=r"(r[1]), "=r"(r[2]), "=r"(r[3]) : "r"(a));
}
__device__ __forceinline__ void ldsm_x2(uint32_t* r, uint32_t a) {
    asm volatile("ldmatrix.sync.aligned.m8n8.x2.shared.b16 {%0,%1}, [%2];"
                 : "=r"(r[0]), "=r"(r[1]) : "r"(a));
}
__device__ __forceinline__ void ldsm_x2t(uint32_t* r, uint32_t a) {
    asm volatile("ldmatrix.sync.aligned.m8n8.x2.trans.shared.b16 {%0,%1}, [%2];"
                 : "=r"(r[0]), "=r"(r[1]) : "r"(a));
}
__device__ __forceinline__ void cp16(uint32_t dst, const void* src) {
    asm volatile("cp.async.cg.shared.global [%0], [%1], 16;" :: "r"(dst), "l"(src));
}
#define CP_COMMIT() asm volatile("cp.async.commit_group;" ::: "memory")
#define CP_WAIT0()  asm volatile("cp.async.wait_group 0;" ::: "memory")

// ------------------------- fp16 projection kernel --------------------------
// D[o][p] = relu(BN(sum_c W[o,c] X[c,p])).  A = W (ldsm x4), B = X (ldsm x2t).
// grid (128, B), 256 thr / 8 warps; warp: o rows [32*(wid>>1)), px [64*(wid&1)).
#define WSOFF 8704                    // Xs [32][136]h = 8704 B, then Ws [128][40]h
#define PROJ_SMEM (128 * 132 * 4)     // Fs overlay dominates

template<int CIN, bool F32OUT, bool QSC>
__global__ __launch_bounds__(256)
void proj_kernel(const float* __restrict__ x, const float* __restrict__ w,
                 const float* __restrict__ gamma, const float* __restrict__ beta,
                 const float* __restrict__ mean, const float* __restrict__ var,
                 float* __restrict__ out32, __half* __restrict__ out16)
{
    extern __shared__ char psm[];
    const uint32_t sbu = smem_u32(psm);
    float* Fs = (float*)psm;                       // [128 px][132 o] (epilogue overlay)
    const int tid = threadIdx.x, wid = tid >> 5, lane = tid & 31;
    const int g = lane >> 2, t4 = lane & 3, l15 = lane & 15;
    const int ob = (wid >> 1) * 32, pb = (wid & 1) * 64;
    const int bb = blockIdx.y, p0 = blockIdx.x * 128;

    float acc[2][8][4];
#pragma unroll
    for (int mt = 0; mt < 2; mt++)
#pragma unroll
        for (int nt = 0; nt < 8; nt++)
#pragma unroll
            for (int r = 0; r < 4; r++) acc[mt][nt][r] = 0.f;

    const float* xb = x + (size_t)bb * CIN * HWP;
    float4 xr[4], wr[4];

    // prefetch chunk 0
#pragma unroll
    for (int t = 0; t < 4; t++) {
        int lin = tid + t * 256;
        xr[t] = *(const float4*)&xb[(size_t)(lin >> 5) * HWP + p0 + (lin & 31) * 4];
        wr[t] = *(const float4*)&w[(size_t)(lin >> 3) * CIN + (lin & 7) * 4];
    }
    // store chunk 0
#pragma unroll
    for (int t = 0; t < 4; t++) {
        int lin = tid + t * 256;
        __half2 h0 = __floats2half2_rn(xr[t].x, xr[t].y);
        __half2 h1 = __floats2half2_rn(xr[t].z, xr[t].w);
        uint2 u; u.x = *(uint32_t*)&h0; u.y = *(uint32_t*)&h1;
        *(uint2*)(psm + (lin >> 5) * 272 + (lin & 31) * 8) = u;
        __half2 g0 = __floats2half2_rn(wr[t].x, wr[t].y);
        __half2 g1 = __floats2half2_rn(wr[t].z, wr[t].w);
        uint2 v; v.x = *(uint32_t*)&g0; v.y = *(uint32_t*)&g1;
        *(uint2*)(psm + WSOFF + (lin >> 3) * 80 + (lin & 7) * 8) = v;
    }
    __syncthreads();

    for (int c0 = 0; c0 < CIN; c0 += 32) {
        const bool nx = (c0 + 32 < CIN);
        if (nx) {
#pragma unroll
            for (int t = 0; t < 4; t++) {
                int lin = tid + t * 256;
                xr[t] = *(const float4*)&xb[(size_t)(c0 + 32 + (lin >> 5)) * HWP + p0 + (lin & 31) * 4];
                wr[t] = *(const float4*)&w[(size_t)(lin >> 3) * CIN + c0 + 32 + (lin & 7) * 4];
            }
        }
#pragma unroll
        for (int ks = 0; ks < 2; ks++) {
            int kc = ks * 16;
            uint32_t a[2][4];
#pragma unroll
            for (int mt = 0; mt < 2; mt++)
                ldsm_x4(a[mt], sbu + WSOFF + (ob + mt * 16 + l15) * 80
                               + (kc + ((lane >> 4) << 3)) * 2);
#pragma unroll
            for (int nt = 0; nt < 8; nt++) {
                uint32_t b[2];
                ldsm_x2t(b, sbu + (kc + l15) * 272 + (pb + nt * 8) * 2);
                mma16816(acc[0][nt], a[0], b);
                mma16816(acc[1][nt], a[1], b);
            }
        }
        __syncthreads();
        if (nx) {
#pragma unroll
            for (int t = 0; t < 4; t++) {
                int lin = tid + t * 256;
                __half2 h0 = __floats2half2_rn(xr[t].x, xr[t].y);
                __half2 h1 = __floats2half2_rn(xr[t].z, xr[t].w);
                uint2 u; u.x = *(uint32_t*)&h0; u.y = *(uint32_t*)&h1;
                *(uint2*)(psm + (lin >> 5) * 272 + (lin & 31) * 8) = u;
                __half2 g0 = __floats2half2_rn(wr[t].x, wr[t].y);
                __half2 g1 = __floats2half2_rn(wr[t].z, wr[t].w);
                uint2 v; v.x = *(uint32_t*)&g0; v.y = *(uint32_t*)&g1;
                *(uint2*)(psm + WSOFF + (lin >> 3) * 80 + (lin & 7) * 8) = v;
            }
            __syncthreads();
        }
    }

    // epilogue: BN + ReLU -> Fs[px][o] (stride 132: conflict-free)
#pragma unroll
    for (int mt = 0; mt < 2; mt++) {
        int r0 = ob + mt * 16 + g, r1 = r0 + 8;
        float s0 = gamma[r0] * rsqrtf(var[r0] + EPSBN);
        float h0 = beta[r0] - mean[r0] * s0;
        float s1 = gamma[r1] * rsqrtf(var[r1] + EPSBN);
        float h1 = beta[r1] - mean[r1] * s1;
#pragma unroll
        for (int nt = 0; nt < 8; nt++) {
            int p = pb + nt * 8 + 2 * t4;
            Fs[p * 132 + r0]       = fmaxf(fmaf(acc[mt][nt][0], s0, h0), 0.f);
            Fs[(p + 1) * 132 + r0] = fmaxf(fmaf(acc[mt][nt][1], s0, h0), 0.f);
            Fs[p * 132 + r1]       = fmaxf(fmaf(acc[mt][nt][2], s1, h1), 0.f);
            Fs[(p + 1) * 132 + r1] = fmaxf(fmaf(acc[mt][nt][3], s1, h1), 0.f);
        }
    }
    __syncthreads();
#pragma unroll
    for (int t = 0; t < 16; t++) {
        int lin = tid + t * 256, row = lin >> 5, c4 = lin & 31;
        float4 v = *(const float4*)&Fs[row * 132 + c4 * 4];
        size_t base = ((size_t)bb * HWP + p0 + row) * CO + c4 * 4;
        if (F32OUT) *(float4*)&out32[base] = v;
        float sc = QSC ? SCALE : 1.f;
        __half2 h0 = __floats2half2_rn(v.x * sc, v.y * sc);
        __half2 h1 = __floats2half2_rn(v.z * sc, v.w * sc);
        uint2 u; u.x = *(uint32_t*)&h0; u.y = *(uint32_t*)&h1;
        *(uint2*)&out16[base] = u;
    }
}

// --------------------- fp16 warp-specialized flash attention ---------------
// Identical structure to R5 (passing), but Q/K tiles arrive via cp.async from
// pre-converted fp16 gmem (Q pre-scaled in proj).
#define NIT   32
#define CR0B  0
#define CR1B  512
#define LBB   1024
#define QB    2048
#define KB    36864
#define KBUFB 17408
#define PB    106496
#define PBUFB 18432
#define ATTN_SMEM 143360
#define QLDB  272
#define PLDB  144

__device__ __forceinline__ void fill_k_async(uint32_t sbu, const __half* kb, int buf, int tid) {
    uint32_t kd = sbu + KB + (uint32_t)buf * KBUFB;
#pragma unroll
    for (int t = 0; t < 3; t++) {
        int lin = tid + t * 384;
        if (lin < 1024) {
            int row = lin >> 4, j = lin & 15;
            cp16(kd + row * QLDB + j * 16, kb + (size_t)row * CO + j * 8);
        }
    }
}

__global__ __launch_bounds__(384)
void attn_kernel(const __half* __restrict__ qh, const __half* __restrict__ kh,
                 const float* __restrict__ imgp, const float* __restrict__ mw,
                 float* __restrict__ out)
{
    extern __shared__ char smc[];
    const uint32_t sbu = smem_u32(smc);
    float* crb[2] = { (float*)(smc + CR0B), (float*)(smc + CR1B) };
    float* lbuf   = (float*)(smc + LBB);
    const int tid = threadIdx.x, wid = tid >> 5, lane = tid & 31;
    const int g = lane >> 2, t4 = lane & 3;
    const int l15 = lane & 15, l7 = lane & 7;
    const int chunk = blockIdx.y, bb = blockIdx.z;
    const int pq0 = chunk * CHUNKP + blockIdx.x * 128;

    // async Q + K0 fills
    const __half* qb = qh + ((size_t)bb * HWP + pq0) * CO;
#pragma unroll
    for (int t = 0; t < 6; t++) {
        int lin = tid + t * 384;
        if (lin < 2048) {
            int row = lin >> 4, j = lin & 15;
            cp16(sbu + QB + row * QLDB + j * 16, qb + (size_t)row * CO + j * 8);
        }
    }
    const __half* ldb = kh + ((size_t)bb * HWP + chunk * CHUNKP) * CO;
    fill_k_async(sbu, ldb, 0, tid);
    CP_COMMIT();

    float acc[2][8][4];
#pragma unroll
    for (int mt = 0; mt < 2; mt++)
#pragma unroll
        for (int nt = 0; nt < 8; nt++)
#pragma unroll
            for (int r = 0; r < 4; r++) acc[mt][nt][r] = 0.f;
    float mrow[4] = {-3.0e38f, -3.0e38f, -3.0e38f, -3.0e38f};
    float lrow[4] = {0.f, 0.f, 0.f, 0.f};

    const int s_mb = (wid & 3) * 32;
    const int o_mb = ((wid - 4) & 3) * 32;
    const int o_db = ((wid - 4) >> 2) * 64;

    CP_WAIT0();
    __syncthreads();

    for (int i = 0; i < NIT; i++) {
        if (i + 1 < NIT) {
            fill_k_async(sbu, ldb + (size_t)(i + 1) * 64 * CO, (i + 1) & 3, tid);
            CP_COMMIT();
        }

        if (wid < 4) {
            // S-warps: S(i) = Q K^T, softmax, P, cr
            const uint32_t kbase = sbu + KB + (uint32_t)(i & 3) * KBUFB;
            const uint32_t qbase = sbu + QB;
#pragma unroll
            for (int mt = 0; mt < 2; mt++)
#pragma unroll
                for (int nt = 0; nt < 8; nt++)
#pragma unroll
                    for (int r = 0; r < 4; r++) acc[mt][nt][r] = 0.f;
#pragma unroll
            for (int ks = 0; ks < 8; ks++) {
                int kc = ks * 16;
                uint32_t qa0[4], qa1[4];
                int acol = kc + ((lane >> 4) << 3);
                ldsm_x4(qa0, qbase + (s_mb + l15) * QLDB + acol * 2);
                ldsm_x4(qa1, qbase + (s_mb + 16 + l15) * QLDB + acol * 2);
                int bcol = kc + (((lane >> 3) & 1) << 3);
#pragma unroll
                for (int nt = 0; nt < 8; nt++) {
                    uint32_t b[2];
                    ldsm_x2(b, kbase + (nt * 8 + l7) * QLDB + bcol * 2);
                    mma16816(acc[0][nt], qa0, b);
                    mma16816(acc[1][nt], qa1, b);
                }
            }
            char* pdst = smc + PB + (i & 1) * PBUFB;
            float* crw = crb[i & 1];
#pragma unroll
            for (int mt = 0; mt < 2; mt++)
#pragma unroll
                for (int h = 0; h < 2; h++) {
                    int s = 2 * mt + h;
                    int row = s_mb + 16 * mt + 8 * h + g;
                    float rm = -3.0e38f;
#pragma unroll
                    for (int nt = 0; nt < 8; nt++)
                        rm = fmaxf(rm, fmaxf(acc[mt][nt][2 * h], acc[mt][nt][2 * h + 1]));
                    rm = fmaxf(rm, __shfl_xor_sync(0xffffffffu, rm, 1));
                    rm = fmaxf(rm, __shfl_xor_sync(0xffffffffu, rm, 2));
                    float mn = fmaxf(mrow[s], rm);
                    float cr = __expf(mrow[s] - mn);
                    mrow[s] = mn;
                    float ps = 0.f;
#pragma unroll
                    for (int nt = 0; nt < 8; nt++) {
                        float p0 = __expf(acc[mt][nt][2 * h] - mn);
                        float p1 = __expf(acc[mt][nt][2 * h + 1] - mn);
                        ps += p0 + p1;
                        __half2 hp = __floats2half2_rn(p0, p1);
                        *(uint32_t*)(pdst + row * PLDB + (nt * 8 + 2 * t4) * 2) = *(uint32_t*)&hp;
                    }
                    ps += __shfl_xor_sync(0xffffffffu, ps, 1);
                    ps += __shfl_xor_sync(0xffffffffu, ps, 2);
                    lrow[s] = lrow[s] * cr + ps;
                    if (t4 == 0) crw[row] = cr;
                }
        } else if (i > 0) {
            // O-warps: O = O*cr(i-1) + P(i-1) K(i-1)
            const int j = i - 1;
            const float* crr = crb[j & 1];
            float crv[4];
#pragma unroll
            for (int s = 0; s < 4; s++)
                crv[s] = crr[o_mb + 16 * (s >> 1) + 8 * (s & 1) + g];
#pragma unroll
            for (int mt = 0; mt < 2; mt++)
#pragma unroll
                for (int nt = 0; nt < 8; nt++)
#pragma unroll
                    for (int h = 0; h < 2; h++) {
                        acc[mt][nt][2 * h]     *= crv[2 * mt + h];
                        acc[mt][nt][2 * h + 1] *= crv[2 * mt + h];
                    }
            const uint32_t pbase = sbu + PB + (uint32_t)(j & 1) * PBUFB;
            const uint32_t kbase = sbu + KB + (uint32_t)(j & 3) * KBUFB;
#pragma unroll
            for (int kq = 0; kq < 4; kq++) {
                int kbv = kq * 16;
                uint32_t pa0[4], pa1[4];
                int acol = kbv + ((lane >> 4) << 3);
                ldsm_x4(pa0, pbase + (o_mb + l15) * PLDB + acol * 2);
                ldsm_x4(pa1, pbase + (o_mb + 16 + l15) * PLDB + acol * 2);
#pragma unroll
                for (int nt = 0; nt < 8; nt++) {
                    uint32_t b[2];
                    ldsm_x2t(b, kbase + (kbv + l15) * QLDB + (o_db + nt * 8) * 2);
                    mma16816(acc[0][nt], pa0, b);
                    mma16816(acc[1][nt], pa1, b);
                }
            }
        }
        CP_WAIT0();
        __syncthreads();
    }

    if (wid < 4) {
        if (t4 == 0) {
#pragma unroll
            for (int s = 0; s < 4; s++)
                lbuf[s_mb + 16 * (s >> 1) + 8 * (s & 1) + g] = lrow[s];
        }
    }
    __syncthreads();

    float e0 = __expf(mw[0]), e1 = __expf(mw[1]);
    float w0 = e0 / (e0 + e1), w1 = e1 / (e0 + e1);
    float* fs2 = (float*)(smc + KB);

    if (wid >= 4) {
        const int j = NIT - 1;
        const float* crr = crb[j & 1];
        float crv[4];
#pragma unroll
        for (int s = 0; s < 4; s++)
            crv[s] = crr[o_mb + 16 * (s >> 1) + 8 * (s & 1) + g];
#pragma unroll
        for (int mt = 0; mt < 2; mt++)
#pragma unroll
            for (int nt = 0; nt < 8; nt++)
#pragma unroll
                for (int h = 0; h < 2; h++) {
                    acc[mt][nt][2 * h]     *= crv[2 * mt + h];
                    acc[mt][nt][2 * h + 1] *= crv[2 * mt + h];
                }
        const uint32_t pbase = sbu + PB + (uint32_t)(j & 1) * PBUFB;
        const uint32_t kbase = sbu + KB + (uint32_t)(j & 3) * KBUFB;
#pragma unroll
        for (int kq = 0; kq < 4; kq++) {
            int kbv = kq * 16;
            uint32_t pa0[4], pa1[4];
            int acol = kbv + ((lane >> 4) << 3);
            ldsm_x4(pa0, pbase + (o_mb + l15) * PLDB + acol * 2);
            ldsm_x4(pa1, pbase + (o_mb + 16 + l15) * PLDB + acol * 2);
#pragma unroll
            for (int nt = 0; nt < 8; nt++) {
                uint32_t b[2];
                ldsm_x2t(b, kbase + (kbv + l15) * QLDB + (o_db + nt * 8) * 2);
                mma16816(acc[0][nt], pa0, b);
                mma16816(acc[1][nt], pa1, b);
            }
        }
        float il[4];
#pragma unroll
        for (int s = 0; s < 4; s++)
            il[s] = 1.f / lbuf[o_mb + 16 * (s >> 1) + 8 * (s & 1) + g];
#pragma unroll
        for (int mt = 0; mt < 2; mt++)
#pragma unroll
            for (int h = 0; h < 2; h++) {
                int row = o_mb + 16 * mt + 8 * h + g;
                float sc = il[2 * mt + h];
                const float* ir = imgp + ((size_t)bb * HWP + pq0 + row) * CO;
#pragma unroll
                for (int nt = 0; nt < 8; nt++) {
                    int c = o_db + nt * 8 + 2 * t4;
                    float2 iv = *(const float2*)&ir[c];
                    fs2[c * 136 + row]       = w0 * iv.x + w1 * acc[mt][nt][2 * h] * sc;
                    fs2[(c + 1) * 136 + row] = w0 * iv.y + w1 * acc[mt][nt][2 * h + 1] * sc;
                }
            }
    }
    __syncthreads();

    float* ob = out + (size_t)bb * CO * HWP;
#pragma unroll
    for (int t = 0; t < 11; t++) {
        int lin = tid + t * 384;
        if (lin < 4096) {
            int c = lin >> 5, p4 = lin & 31;
            float4 v = *(const float4*)&fs2[c * 136 + p4 * 4];
            *(float4*)&ob[(size_t)c * HWP + pq0 + p4 * 4] = v;
        }
    }
}

// ---------------------------------------------------------------------------
extern "C" void kernel_launch(void* const* d_in, const int* in_sizes, int n_in,
                              void* d_out, int out_size)
{
    const float* lidar_x = (const float*)d_in[0];
    const float* image_x = (const float*)d_in[1];
    const float* lw = (const float*)d_in[2];
    const float* lg = (const float*)d_in[3];
    const float* lb = (const float*)d_in[4];
    const float* lm = (const float*)d_in[5];
    const float* lv = (const float*)d_in[6];
    const float* iw = (const float*)d_in[7];
    const float* ig = (const float*)d_in[8];
    const float* ib = (const float*)d_in[9];
    const float* im = (const float*)d_in[10];
    const float* iv = (const float*)d_in[11];
    const float* mw = (const float*)d_in[12];
    float* out = (float*)d_out;

    float* ip = nullptr;
    __half *q16 = nullptr, *k16 = nullptr;
    cudaGetSymbolAddress((void**)&ip, g_image_proj);
    cudaGetSymbolAddress((void**)&q16, g_q16);
    cudaGetSymbolAddress((void**)&k16, g_k16);
    cudaFuncSetAttribute(proj_kernel<CLI, false, false>, cudaFuncAttributeMaxDynamicSharedMemorySize, PROJ_SMEM);
    cudaFuncSetAttribute(proj_kernel<CIM, true, true>, cudaFuncAttributeMaxDynamicSharedMemorySize, PROJ_SMEM);
    cudaFuncSetAttribute(attn_kernel, cudaFuncAttributeMaxDynamicSharedMemorySize, ATTN_SMEM);

    dim3 pgrid(HWP / 128, BB);
    proj_kernel<CLI, false, false><<<pgrid, 256, PROJ_SMEM>>>(lidar_x, lw, lg, lb, lm, lv, nullptr, k16);
    proj_kernel<CIM, true, true><<<pgrid, 256, PROJ_SMEM>>>(image_x, iw, ig, ib, im, iv, ip, q16);

    dim3 agrid(CHUNKP / 128, NCHUNK, BB);
    attn_kernel<<<agrid, 384, ATTN_SMEM>>>(q16, k16, ip, mw, out);
}

// round 7
// speedup vs baseline: 7.6082x; 1.4622x over previous
#include <cuda_runtime.h>
#include <cuda_fp16.h>
#include <math.h>
#include <stdint.h>

#define BB     2
#define HWP    16384
#define CO     128
#define CLI    256
#define CIM    512
#define CHUNKP 2048
#define NCHUNK 8
#define EPSBN  1e-5f
#define SCALE  0.08838834764831845f   // 1/sqrt(128)
#define QSCL   (0.08838834764831845f * 1.4426950408889634f)  // SCALE * log2(e)

__device__ __half g_q16[BB * HWP * CO];   // image proj, pre-scaled by SCALE*log2e
__device__ __half g_k16[BB * HWP * CO];   // lidar proj
__device__ float  g_image_proj[BB * HWP * CO];

// ------------------------------ helpers ------------------------------------
__device__ __forceinline__ uint32_t smem_u32(const void* p) {
    uint32_t a;
    asm("{ .reg .u64 t; cvta.to.shared.u64 t, %1; cvt.u32.u64 %0, t; }" : "=r"(a) : "l"(p));
    return a;
}
__device__ __forceinline__ void mma16816(float* c, const uint32_t* a, const uint32_t* b) {
    asm volatile("mma.sync.aligned.m16n8k16.row.col.f32.f16.f16.f32 "
                 "{%0,%1,%2,%3}, {%4,%5,%6,%7}, {%8,%9}, {%0,%1,%2,%3};"
                 : "+f"(c[0]), "+f"(c[1]), "+f"(c[2]), "+f"(c[3])
                 : "r"(a[0]), "r"(a[1]), "r"(a[2]), "r"(a[3]), "r"(b[0]), "r"(b[1]));
}
__device__ __forceinline__ void ldsm_x4(uint32_t* r, uint32_t a) {
    asm volatile("ldmatrix.sync.aligned.m8n8.x4.shared.b16 {%0,%1,%2,%3}, [%4];"
                 : "=r"(r[0]), "=r"(r[1]), "=r"(r[2]), "=r"(r[3]) : "r"(a));
}
__device__ __forceinline__ void ldsm_x2(uint32_t* r, uint32_t a) {
    asm volatile("ldmatrix.sync.aligned.m8n8.x2.shared.b16 {%0,%1}, [%2];"
                 : "=r"(r[0]), "=r"(r[1]) : "r"(a));
}
__device__ __forceinline__ void ldsm_x2t(uint32_t* r, uint32_t a) {
    asm volatile("ldmatrix.sync.aligned.m8n8.x2.trans.shared.b16 {%0,%1}, [%2];"
                 : "=r"(r[0]), "=r"(r[1]) : "r"(a));
}
__device__ __forceinline__ void cp16(uint32_t dst, const void* src) {
    asm volatile("cp.async.cg.shared.global [%0], [%1], 16;" :: "r"(dst), "l"(src));
}
#define CP_COMMIT() asm volatile("cp.async.commit_group;" ::: "memory")
#define CP_WAIT0()  asm volatile("cp.async.wait_group 0;" ::: "memory")
__device__ __forceinline__ float ex2(float x) {
    float y; asm("ex2.approx.ftz.f32 %0, %1;" : "=f"(y) : "f"(x)); return y;
}

// ------------------------- fp16 projection kernel (R6, known-good) ---------
#define WSOFF 8704
#define PROJ_SMEM (128 * 132 * 4)

template<int CIN, bool F32OUT, bool QSC>
__global__ __launch_bounds__(256)
void proj_kernel(const float* __restrict__ x, const float* __restrict__ w,
                 const float* __restrict__ gamma, const float* __restrict__ beta,
                 const float* __restrict__ mean, const float* __restrict__ var,
                 float* __restrict__ out32, __half* __restrict__ out16)
{
    extern __shared__ char psm[];
    const uint32_t sbu = smem_u32(psm);
    float* Fs = (float*)psm;
    const int tid = threadIdx.x, wid = tid >> 5, lane = tid & 31;
    const int g = lane >> 2, t4 = lane & 3, l15 = lane & 15;
    const int ob = (wid >> 1) * 32, pb = (wid & 1) * 64;
    const int bb = blockIdx.y, p0 = blockIdx.x * 128;

    float acc[2][8][4];
#pragma unroll
    for (int mt = 0; mt < 2; mt++)
#pragma unroll
        for (int nt = 0; nt < 8; nt++)
#pragma unroll
            for (int r = 0; r < 4; r++) acc[mt][nt][r] = 0.f;

    const float* xb = x + (size_t)bb * CIN * HWP;
    float4 xr[4], wr[4];
#pragma unroll
    for (int t = 0; t < 4; t++) {
        int lin = tid + t * 256;
        xr[t] = *(const float4*)&xb[(size_t)(lin >> 5) * HWP + p0 + (lin & 31) * 4];
        wr[t] = *(const float4*)&w[(size_t)(lin >> 3) * CIN + (lin & 7) * 4];
    }
#pragma unroll
    for (int t = 0; t < 4; t++) {
        int lin = tid + t * 256;
        __half2 h0 = __floats2half2_rn(xr[t].x, xr[t].y);
        __half2 h1 = __floats2half2_rn(xr[t].z, xr[t].w);
        uint2 u; u.x = *(uint32_t*)&h0; u.y = *(uint32_t*)&h1;
        *(uint2*)(psm + (lin >> 5) * 272 + (lin & 31) * 8) = u;
        __half2 g0 = __floats2half2_rn(wr[t].x, wr[t].y);
        __half2 g1 = __floats2half2_rn(wr[t].z, wr[t].w);
        uint2 v; v.x = *(uint32_t*)&g0; v.y = *(uint32_t*)&g1;
        *(uint2*)(psm + WSOFF + (lin >> 3) * 80 + (lin & 7) * 8) = v;
    }
    __syncthreads();

    for (int c0 = 0; c0 < CIN; c0 += 32) {
        const bool nx = (c0 + 32 < CIN);
        if (nx) {
#pragma unroll
            for (int t = 0; t < 4; t++) {
                int lin = tid + t * 256;
                xr[t] = *(const float4*)&xb[(size_t)(c0 + 32 + (lin >> 5)) * HWP + p0 + (lin & 31) * 4];
                wr[t] = *(const float4*)&w[(size_t)(lin >> 3) * CIN + c0 + 32 + (lin & 7) * 4];
            }
        }
#pragma unroll
        for (int ks = 0; ks < 2; ks++) {
            int kc = ks * 16;
            uint32_t a[2][4];
#pragma unroll
            for (int mt = 0; mt < 2; mt++)
                ldsm_x4(a[mt], sbu + WSOFF + (ob + mt * 16 + l15) * 80
                               + (kc + ((lane >> 4) << 3)) * 2);
#pragma unroll
            for (int nt = 0; nt < 8; nt++) {
                uint32_t b[2];
                ldsm_x2t(b, sbu + (kc + l15) * 272 + (pb + nt * 8) * 2);
                mma16816(acc[0][nt], a[0], b);
                mma16816(acc[1][nt], a[1], b);
            }
        }
        __syncthreads();
        if (nx) {
#pragma unroll
            for (int t = 0; t < 4; t++) {
                int lin = tid + t * 256;
                __half2 h0 = __floats2half2_rn(xr[t].x, xr[t].y);
                __half2 h1 = __floats2half2_rn(xr[t].z, xr[t].w);
                uint2 u; u.x = *(uint32_t*)&h0; u.y = *(uint32_t*)&h1;
                *(uint2*)(psm + (lin >> 5) * 272 + (lin & 31) * 8) = u;
                __half2 g0 = __floats2half2_rn(wr[t].x, wr[t].y);
                __half2 g1 = __floats2half2_rn(wr[t].z, wr[t].w);
                uint2 v; v.x = *(uint32_t*)&g0; v.y = *(uint32_t*)&g1;
                *(uint2*)(psm + WSOFF + (lin >> 3) * 80 + (lin & 7) * 8) = v;
            }
            __syncthreads();
        }
    }

#pragma unroll
    for (int mt = 0; mt < 2; mt++) {
        int r0 = ob + mt * 16 + g, r1 = r0 + 8;
        float s0 = gamma[r0] * rsqrtf(var[r0] + EPSBN);
        float h0 = beta[r0] - mean[r0] * s0;
        float s1 = gamma[r1] * rsqrtf(var[r1] + EPSBN);
        float h1 = beta[r1] - mean[r1] * s1;
#pragma unroll
        for (int nt = 0; nt < 8; nt++) {
            int p = pb + nt * 8 + 2 * t4;
            Fs[p * 132 + r0]       = fmaxf(fmaf(acc[mt][nt][0], s0, h0), 0.f);
            Fs[(p + 1) * 132 + r0] = fmaxf(fmaf(acc[mt][nt][1], s0, h0), 0.f);
            Fs[p * 132 + r1]       = fmaxf(fmaf(acc[mt][nt][2], s1, h1), 0.f);
            Fs[(p + 1) * 132 + r1] = fmaxf(fmaf(acc[mt][nt][3], s1, h1), 0.f);
        }
    }
    __syncthreads();
#pragma unroll
    for (int t = 0; t < 16; t++) {
        int lin = tid + t * 256, row = lin >> 5, c4 = lin & 31;
        float4 v = *(const float4*)&Fs[row * 132 + c4 * 4];
        size_t base = ((size_t)bb * HWP + p0 + row) * CO + c4 * 4;
        if (F32OUT) *(float4*)&out32[base] = v;
        float sc = QSC ? QSCL : 1.f;
        __half2 h0 = __floats2half2_rn(v.x * sc, v.y * sc);
        __half2 h1 = __floats2half2_rn(v.z * sc, v.w * sc);
        uint2 u; u.x = *(uint32_t*)&h0; u.y = *(uint32_t*)&h1;
        *(uint2*)&out16[base] = u;
    }
}

// --------------- FA2 register-P flash attention (256 thr, 8 warps) ---------
// TQ=128 (m16/warp), TK=64, D=128. grid (16, 8, 2).
// smem: Q [128][136h] @0 (only until Q->regs), K 4 x [64][136h] @34816.
// Epilogue staging [128c][132p]f32 overlays everything.
#define NIT   32
#define KB    34816
#define KBUFB 17408
#define ATTN_SMEM (KB + 4 * KBUFB)
#define QLDB  272

__device__ __forceinline__ void fill_k_async(uint32_t sbu, const __half* kb, int buf, int tid) {
    uint32_t kd = sbu + KB + (uint32_t)buf * KBUFB;
#pragma unroll
    for (int t = 0; t < 4; t++) {
        int lin = tid + t * 256;
        int row = lin >> 4, j = lin & 15;
        cp16(kd + row * QLDB + j * 16, kb + (size_t)row * CO + j * 8);
    }
}

__global__ __launch_bounds__(256, 1)
void attn_kernel(const __half* __restrict__ qh, const __half* __restrict__ kh,
                 const float* __restrict__ imgp, const float* __restrict__ mw,
                 float* __restrict__ out)
{
    extern __shared__ char smc[];
    const uint32_t sbu = smem_u32(smc);
    const int tid = threadIdx.x, wid = tid >> 5, lane = tid & 31;
    const int g = lane >> 2, t4 = lane & 3;
    const int l15 = lane & 15, l7 = lane & 7;
    const int chunk = blockIdx.y, bb = blockIdx.z;
    const int pq0 = chunk * CHUNKP + blockIdx.x * 128;
    const int mb = wid * 16;

    // async Q + K0 fills
    const __half* qb = qh + ((size_t)bb * HWP + pq0) * CO;
#pragma unroll
    for (int t = 0; t < 8; t++) {
        int lin = tid + t * 256;
        int row = lin >> 4, j = lin & 15;
        cp16(sbu + row * QLDB + j * 16, qb + (size_t)row * CO + j * 8);
    }
    const __half* ldb = kh + ((size_t)bb * HWP + chunk * CHUNKP) * CO;
    fill_k_async(sbu, ldb, 0, tid);
    CP_COMMIT();
    CP_WAIT0();
    __syncthreads();

    // Q -> registers (A fragments for all 8 k-steps), Q smem dead afterwards
    uint32_t qa[8][4];
#pragma unroll
    for (int ks = 0; ks < 8; ks++)
        ldsm_x4(qa[ks], sbu + (mb + l15) * QLDB + (ks * 16 + ((lane >> 4) << 3)) * 2);
    __syncthreads();   // everyone done reading Q before K fills could... (K separate region; kept for safety vs staging aliasing at end only)

    float oc[16][4];
#pragma unroll
    for (int nt = 0; nt < 16; nt++)
#pragma unroll
        for (int r = 0; r < 4; r++) oc[nt][r] = 0.f;
    float m0 = -3.0e38f, m1 = -3.0e38f, l0 = 0.f, l1 = 0.f;

    for (int i = 0; i < NIT; i++) {
        if (i + 1 < NIT) {
            fill_k_async(sbu, ldb + (size_t)(i + 1) * 64 * CO, (i + 1) & 3, tid);
            CP_COMMIT();
        }
        const uint32_t kbase = sbu + KB + (uint32_t)(i & 3) * KBUFB;

        // ---- S = Q K^T (m16 x n64), logits already in log2 domain ----
        float sc[8][4];
#pragma unroll
        for (int nt = 0; nt < 8; nt++)
#pragma unroll
            for (int r = 0; r < 4; r++) sc[nt][r] = 0.f;
#pragma unroll
        for (int ks = 0; ks < 8; ks++) {
            int bcol = ks * 16 + ((lane >> 3) & 1) * 8;
#pragma unroll
            for (int nt = 0; nt < 8; nt++) {
                uint32_t b[2];
                ldsm_x2(b, kbase + (nt * 8 + l7) * QLDB + bcol * 2);
                mma16816(sc[nt], qa[ks], b);
            }
        }

        // ---- softmax (rows mb+g, mb+8+g), all register/shuffle ----
        float rm0 = -3.0e38f, rm1 = -3.0e38f;
#pragma unroll
        for (int nt = 0; nt < 8; nt++) {
            rm0 = fmaxf(rm0, fmaxf(sc[nt][0], sc[nt][1]));
            rm1 = fmaxf(rm1, fmaxf(sc[nt][2], sc[nt][3]));
        }
        rm0 = fmaxf(rm0, __shfl_xor_sync(0xffffffffu, rm0, 1));
        rm0 = fmaxf(rm0, __shfl_xor_sync(0xffffffffu, rm0, 2));
        rm1 = fmaxf(rm1, __shfl_xor_sync(0xffffffffu, rm1, 1));
        rm1 = fmaxf(rm1, __shfl_xor_sync(0xffffffffu, rm1, 2));
        float mn0 = fmaxf(m0, rm0), mn1 = fmaxf(m1, rm1);
        float cr0 = ex2(m0 - mn0), cr1 = ex2(m1 - mn1);
        m0 = mn0; m1 = mn1;

        uint32_t ph[8][2];
        float ps0 = 0.f, ps1 = 0.f;
#pragma unroll
        for (int nt = 0; nt < 8; nt++) {
            float p0 = ex2(sc[nt][0] - mn0);
            float p1 = ex2(sc[nt][1] - mn0);
            float p2 = ex2(sc[nt][2] - mn1);
            float p3 = ex2(sc[nt][3] - mn1);
            ps0 += p0 + p1; ps1 += p2 + p3;
            __half2 hA = __floats2half2_rn(p0, p1);
            __half2 hB = __floats2half2_rn(p2, p3);
            ph[nt][0] = *(uint32_t*)&hA;   // row g
            ph[nt][1] = *(uint32_t*)&hB;   // row g+8
        }
        ps0 += __shfl_xor_sync(0xffffffffu, ps0, 1);
        ps0 += __shfl_xor_sync(0xffffffffu, ps0, 2);
        ps1 += __shfl_xor_sync(0xffffffffu, ps1, 1);
        ps1 += __shfl_xor_sync(0xffffffffu, ps1, 2);
        l0 = l0 * cr0 + ps0;
        l1 = l1 * cr1 + ps1;

        // ---- O rescale + O += P K (P stays in registers as A-frags) ----
#pragma unroll
        for (int nt = 0; nt < 16; nt++) {
            oc[nt][0] *= cr0; oc[nt][1] *= cr0;
            oc[nt][2] *= cr1; oc[nt][3] *= cr1;
        }
#pragma unroll
        for (int kq = 0; kq < 4; kq++) {
            uint32_t pa[4] = { ph[2 * kq][0], ph[2 * kq][1],
                               ph[2 * kq + 1][0], ph[2 * kq + 1][1] };
#pragma unroll
            for (int nt = 0; nt < 16; nt++) {
                uint32_t b[2];
                ldsm_x2t(b, kbase + (kq * 16 + l15) * QLDB + (nt * 8) * 2);
                mma16816(oc[nt], pa, b);
            }
        }
        CP_WAIT0();
        __syncthreads();
    }

    // ---- blend epilogue: fused = O/l; out = w0*img + w1*fused ----
    float e0 = __expf(mw[0]), e1 = __expf(mw[1]);
    float w0 = e0 / (e0 + e1), w1 = e1 / (e0 + e1);
    float il0 = 1.f / l0, il1 = 1.f / l1;
    int r0 = mb + g, r1 = mb + 8 + g;
    float* stg = (float*)smc;   // [128 c][132 p] overlays Q+K (all dead)
    const float* ir0 = imgp + ((size_t)bb * HWP + pq0 + r0) * CO;
    const float* ir1 = imgp + ((size_t)bb * HWP + pq0 + r1) * CO;
    __syncthreads();
#pragma unroll
    for (int nt = 0; nt < 16; nt++) {
        int c = nt * 8 + 2 * t4;
        float2 i0 = *(const float2*)&ir0[c];
        float2 i1 = *(const float2*)&ir1[c];
        stg[c * 132 + r0]       = w0 * i0.x + w1 * oc[nt][0] * il0;
        stg[(c + 1) * 132 + r0] = w0 * i0.y + w1 * oc[nt][1] * il0;
        stg[c * 132 + r1]       = w0 * i1.x + w1 * oc[nt][2] * il1;
        stg[(c + 1) * 132 + r1] = w0 * i1.y + w1 * oc[nt][3] * il1;
    }
    __syncthreads();

    float* ob = out + (size_t)bb * CO * HWP;
#pragma unroll
    for (int t = 0; t < 16; t++) {
        int lin = tid + t * 256;
        int c = lin >> 5, p4 = lin & 31;
        float4 v = *(const float4*)&stg[c * 132 + p4 * 4];
        *(float4*)&ob[(size_t)c * HWP + pq0 + p4 * 4] = v;
    }
}

// ---------------------------------------------------------------------------
extern "C" void kernel_launch(void* const* d_in, const int* in_sizes, int n_in,
                              void* d_out, int out_size)
{
    const float* lidar_x = (const float*)d_in[0];
    const float* image_x = (const float*)d_in[1];
    const float* lw = (const float*)d_in[2];
    const float* lg = (const float*)d_in[3];
    const float* lb = (const float*)d_in[4];
    const float* lm = (const float*)d_in[5];
    const float* lv = (const float*)d_in[6];
    const float* iw = (const float*)d_in[7];
    const float* ig = (const float*)d_in[8];
    const float* ib = (const float*)d_in[9];
    const float* im = (const float*)d_in[10];
    const float* iv = (const float*)d_in[11];
    const float* mw = (const float*)d_in[12];
    float* out = (float*)d_out;

    float* ip = nullptr;
    __half *q16 = nullptr, *k16 = nullptr;
    cudaGetSymbolAddress((void**)&ip, g_image_proj);
    cudaGetSymbolAddress((void**)&q16, g_q16);
    cudaGetSymbolAddress((void**)&k16, g_k16);
    cudaFuncSetAttribute(proj_kernel<CLI, false, false>, cudaFuncAttributeMaxDynamicSharedMemorySize, PROJ_SMEM);
    cudaFuncSetAttribute(proj_kernel<CIM, true, true>, cudaFuncAttributeMaxDynamicSharedMemorySize, PROJ_SMEM);
    cudaFuncSetAttribute(attn_kernel, cudaFuncAttributeMaxDynamicSharedMemorySize, ATTN_SMEM);

    dim3 pgrid(HWP / 128, BB);
    proj_kernel<CLI, false, false><<<pgrid, 256, PROJ_SMEM>>>(lidar_x, lw, lg, lb, lm, lv, nullptr, k16);
    proj_kernel<CIM, true, true><<<pgrid, 256, PROJ_SMEM>>>(image_x, iw, ig, ib, im, iv, ip, q16);

    dim3 agrid(CHUNKP / 128, NCHUNK, BB);
    attn_kernel<<<agrid, 256, ATTN_SMEM>>>(q16, k16, ip, mw, out);
}

// round 8
// speedup vs baseline: 7.6333x; 1.0033x over previous
#include <cuda_runtime.h>
#include <cuda_fp16.h>
#include <math.h>
#include <stdint.h>

#define BB     2
#define HWP    16384
#define CO     128
#define CLI    256
#define CIM    512
#define CHUNKP 2048
#define NCHUNK 8
#define EPSBN  1e-5f
#define SCALE  0.08838834764831845f   // 1/sqrt(128)
#define QSCL   (0.08838834764831845f * 1.4426950408889634f)  // SCALE * log2(e)

__device__ __half g_q16[BB * HWP * CO];   // image proj, pre-scaled by SCALE*log2e
__device__ __half g_k16[BB * HWP * CO];   // lidar proj
__device__ float  g_image_proj[BB * HWP * CO];

// ------------------------------ helpers ------------------------------------
__device__ __forceinline__ uint32_t smem_u32(const void* p) {
    uint32_t a;
    asm("{ .reg .u64 t; cvta.to.shared.u64 t, %1; cvt.u32.u64 %0, t; }" : "=r"(a) : "l"(p));
    return a;
}
__device__ __forceinline__ void mma16816(float* c, const uint32_t* a, const uint32_t* b) {
    asm volatile("mma.sync.aligned.m16n8k16.row.col.f32.f16.f16.f32 "
                 "{%0,%1,%2,%3}, {%4,%5,%6,%7}, {%8,%9}, {%0,%1,%2,%3};"
                 : "+f"(c[0]), "+f"(c[1]), "+f"(c[2]), "+f"(c[3])
                 : "r"(a[0]), "r"(a[1]), "r"(a[2]), "r"(a[3]), "r"(b[0]), "r"(b[1]));
}
__device__ __forceinline__ void ldsm_x4(uint32_t* r, uint32_t a) {
    asm volatile("ldmatrix.sync.aligned.m8n8.x4.shared.b16 {%0,%1,%2,%3}, [%4];"
                 : "=r"(r[0]), "=r"(r[1]), "=r"(r[2]), "=r"(r[3]) : "r"(a));
}
__device__ __forceinline__ void ldsm_x4t(uint32_t* r, uint32_t a) {
    asm volatile("ldmatrix.sync.aligned.m8n8.x4.trans.shared.b16 {%0,%1,%2,%3}, [%4];"
                 : "=r"(r[0]), "=r"(r[1]), "=r"(r[2]), "=r"(r[3]) : "r"(a));
}
__device__ __forceinline__ void ldsm_x2t(uint32_t* r, uint32_t a) {
    asm volatile("ldmatrix.sync.aligned.m8n8.x2.trans.shared.b16 {%0,%1}, [%2];"
                 : "=r"(r[0]), "=r"(r[1]) : "r"(a));
}
__device__ __forceinline__ void cp16(uint32_t dst, const void* src) {
    asm volatile("cp.async.cg.shared.global [%0], [%1], 16;" :: "r"(dst), "l"(src));
}
#define CP_COMMIT() asm volatile("cp.async.commit_group;" ::: "memory")
#define CP_WAIT0()  asm volatile("cp.async.wait_group 0;" ::: "memory")
__device__ __forceinline__ float ex2(float x) {
    float y; asm("ex2.approx.ftz.f32 %0, %1;" : "=f"(y) : "f"(x)); return y;
}

// ------------------------- fp16 projection kernel --------------------------
// v2: no register prefetch; 2 CTAs/SM for latency hiding.
#define WSOFF 8704
#define PROJ_SMEM (128 * 132 * 4)

template<int CIN, bool F32OUT, bool QSC>
__global__ __launch_bounds__(256, 2)
void proj_kernel(const float* __restrict__ x, const float* __restrict__ w,
                 const float* __restrict__ gamma, const float* __restrict__ beta,
                 const float* __restrict__ mean, const float* __restrict__ var,
                 float* __restrict__ out32, __half* __restrict__ out16)
{
    extern __shared__ char psm[];
    const uint32_t sbu = smem_u32(psm);
    float* Fs = (float*)psm;
    const int tid = threadIdx.x, wid = tid >> 5, lane = tid & 31;
    const int g = lane >> 2, t4 = lane & 3, l15 = lane & 15;
    const int ob = (wid >> 1) * 32, pb = (wid & 1) * 64;
    const int bb = blockIdx.y, p0 = blockIdx.x * 128;

    float acc[2][8][4];
#pragma unroll
    for (int mt = 0; mt < 2; mt++)
#pragma unroll
        for (int nt = 0; nt < 8; nt++)
#pragma unroll
            for (int r = 0; r < 4; r++) acc[mt][nt][r] = 0.f;

    const float* xb = x + (size_t)bb * CIN * HWP;

    for (int c0 = 0; c0 < CIN; c0 += 32) {
        __syncthreads();
#pragma unroll
        for (int t = 0; t < 4; t++) {
            int lin = tid + t * 256;
            float4 xv = *(const float4*)&xb[(size_t)(c0 + (lin >> 5)) * HWP + p0 + (lin & 31) * 4];
            __half2 h0 = __floats2half2_rn(xv.x, xv.y);
            __half2 h1 = __floats2half2_rn(xv.z, xv.w);
            uint2 u; u.x = *(uint32_t*)&h0; u.y = *(uint32_t*)&h1;
            *(uint2*)(psm + (lin >> 5) * 272 + (lin & 31) * 8) = u;
            float4 wv = *(const float4*)&w[(size_t)(lin >> 3) * CIN + c0 + (lin & 7) * 4];
            __half2 g0 = __floats2half2_rn(wv.x, wv.y);
            __half2 g1 = __floats2half2_rn(wv.z, wv.w);
            uint2 v; v.x = *(uint32_t*)&g0; v.y = *(uint32_t*)&g1;
            *(uint2*)(psm + WSOFF + (lin >> 3) * 80 + (lin & 7) * 8) = v;
        }
        __syncthreads();
#pragma unroll
        for (int ks = 0; ks < 2; ks++) {
            int kc = ks * 16;
            uint32_t a[2][4];
#pragma unroll
            for (int mt = 0; mt < 2; mt++)
                ldsm_x4(a[mt], sbu + WSOFF + (ob + mt * 16 + l15) * 80
                               + (kc + ((lane >> 4) << 3)) * 2);
#pragma unroll
            for (int nt = 0; nt < 8; nt++) {
                uint32_t b[2];
                ldsm_x2t(b, sbu + (kc + l15) * 272 + (pb + nt * 8) * 2);
                mma16816(acc[0][nt], a[0], b);
                mma16816(acc[1][nt], a[1], b);
            }
        }
    }
    __syncthreads();

    // epilogue: BN + ReLU -> Fs[px][o]
#pragma unroll
    for (int mt = 0; mt < 2; mt++) {
        int r0 = ob + mt * 16 + g, r1 = r0 + 8;
        float s0 = gamma[r0] * rsqrtf(var[r0] + EPSBN);
        float h0 = beta[r0] - mean[r0] * s0;
        float s1 = gamma[r1] * rsqrtf(var[r1] + EPSBN);
        float h1 = beta[r1] - mean[r1] * s1;
#pragma unroll
        for (int nt = 0; nt < 8; nt++) {
            int p = pb + nt * 8 + 2 * t4;
            Fs[p * 132 + r0]       = fmaxf(fmaf(acc[mt][nt][0], s0, h0), 0.f);
            Fs[(p + 1) * 132 + r0] = fmaxf(fmaf(acc[mt][nt][1], s0, h0), 0.f);
            Fs[p * 132 + r1]       = fmaxf(fmaf(acc[mt][nt][2], s1, h1), 0.f);
            Fs[(p + 1) * 132 + r1] = fmaxf(fmaf(acc[mt][nt][3], s1, h1), 0.f);
        }
    }
    __syncthreads();
#pragma unroll
    for (int t = 0; t < 16; t++) {
        int lin = tid + t * 256, row = lin >> 5, c4 = lin & 31;
        float4 v = *(const float4*)&Fs[row * 132 + c4 * 4];
        size_t base = ((size_t)bb * HWP + p0 + row) * CO + c4 * 4;
        if (F32OUT) *(float4*)&out32[base] = v;
        float sc = QSC ? QSCL : 1.f;
        __half2 h0 = __floats2half2_rn(v.x * sc, v.y * sc);
        __half2 h1 = __floats2half2_rn(v.z * sc, v.w * sc);
        uint2 u; u.x = *(uint32_t*)&h0; u.y = *(uint32_t*)&h1;
        *(uint2*)&out16[base] = u;
    }
}

// --------------- FA2 register-P flash attention (256 thr, 8 warps) ---------
// TQ=128 (m16/warp), TK=64, D=128. grid (16, 8, 2). ldsm x4 everywhere.
#define NIT   32
#define KB    34816
#define KBUFB 17408
#define ATTN_SMEM (KB + 4 * KBUFB)
#define QLDB  272

__device__ __forceinline__ void fill_k_async(uint32_t sbu, const __half* kb, int buf, int tid) {
    uint32_t kd = sbu + KB + (uint32_t)buf * KBUFB;
#pragma unroll
    for (int t = 0; t < 4; t++) {
        int lin = tid + t * 256;
        int row = lin >> 4, j = lin & 15;
        cp16(kd + row * QLDB + j * 16, kb + (size_t)row * CO + j * 8);
    }
}

__global__ __launch_bounds__(256, 1)
void attn_kernel(const __half* __restrict__ qh, const __half* __restrict__ kh,
                 const float* __restrict__ imgp, const float* __restrict__ mw,
                 float* __restrict__ out)
{
    extern __shared__ char smc[];
    const uint32_t sbu = smem_u32(smc);
    const int tid = threadIdx.x, wid = tid >> 5, lane = tid & 31;
    const int g = lane >> 2, t4 = lane & 3;
    const int l15 = lane & 15, l7 = lane & 7;
    const int chunk = blockIdx.y, bb = blockIdx.z;
    const int pq0 = chunk * CHUNKP + blockIdx.x * 128;
    const int mb = wid * 16;

    // async Q + K0 fills
    const __half* qb = qh + ((size_t)bb * HWP + pq0) * CO;
#pragma unroll
    for (int t = 0; t < 8; t++) {
        int lin = tid + t * 256;
        int row = lin >> 4, j = lin & 15;
        cp16(sbu + row * QLDB + j * 16, qb + (size_t)row * CO + j * 8);
    }
    const __half* ldb = kh + ((size_t)bb * HWP + chunk * CHUNKP) * CO;
    fill_k_async(sbu, ldb, 0, tid);
    CP_COMMIT();
    CP_WAIT0();
    __syncthreads();

    // Q -> registers (A fragments for all 8 k-steps)
    uint32_t qa[8][4];
#pragma unroll
    for (int ks = 0; ks < 8; ks++)
        ldsm_x4(qa[ks], sbu + (mb + l15) * QLDB + (ks * 16 + ((lane >> 4) << 3)) * 2);
    __syncthreads();

    float oc[16][4];
#pragma unroll
    for (int nt = 0; nt < 16; nt++)
#pragma unroll
        for (int r = 0; r < 4; r++) oc[nt][r] = 0.f;
    float m0 = -3.0e38f, m1 = -3.0e38f, l0 = 0.f, l1 = 0.f;

    for (int i = 0; i < NIT; i++) {
        if (i + 1 < NIT) {
            fill_k_async(sbu, ldb + (size_t)(i + 1) * 64 * CO, (i + 1) & 3, tid);
            CP_COMMIT();
        }
        const uint32_t kbase = sbu + KB + (uint32_t)(i & 3) * KBUFB;

        // ---- S = Q K^T (m16 x n64), x4 B-loads (2 n-tiles per ldsm) ----
        float sc[8][4];
#pragma unroll
        for (int nt = 0; nt < 8; nt++)
#pragma unroll
            for (int r = 0; r < 4; r++) sc[nt][r] = 0.f;
#pragma unroll
        for (int ks = 0; ks < 8; ks++) {
            uint32_t brow = (uint32_t)(l7 + ((lane >> 4) << 3));
            uint32_t bcol = (uint32_t)(ks * 16 + ((lane >> 3) & 1) * 8);
#pragma unroll
            for (int ntp = 0; ntp < 4; ntp++) {
                uint32_t b4[4];
                ldsm_x4(b4, kbase + (ntp * 16 + brow) * QLDB + bcol * 2);
                mma16816(sc[2 * ntp], qa[ks], b4);
                mma16816(sc[2 * ntp + 1], qa[ks], b4 + 2);
            }
        }

        // ---- softmax (rows mb+g, mb+8+g), log2 domain ----
        float rm0 = -3.0e38f, rm1 = -3.0e38f;
#pragma unroll
        for (int nt = 0; nt < 8; nt++) {
            rm0 = fmaxf(rm0, fmaxf(sc[nt][0], sc[nt][1]));
            rm1 = fmaxf(rm1, fmaxf(sc[nt][2], sc[nt][3]));
        }
        rm0 = fmaxf(rm0, __shfl_xor_sync(0xffffffffu, rm0, 1));
        rm0 = fmaxf(rm0, __shfl_xor_sync(0xffffffffu, rm0, 2));
        rm1 = fmaxf(rm1, __shfl_xor_sync(0xffffffffu, rm1, 1));
        rm1 = fmaxf(rm1, __shfl_xor_sync(0xffffffffu, rm1, 2));
        float mn0 = fmaxf(m0, rm0), mn1 = fmaxf(m1, rm1);
        float cr0 = ex2(m0 - mn0), cr1 = ex2(m1 - mn1);
        m0 = mn0; m1 = mn1;

        uint32_t ph[8][2];
        float ps0 = 0.f, ps1 = 0.f;
#pragma unroll
        for (int nt = 0; nt < 8; nt++) {
            float p0 = ex2(sc[nt][0] - mn0);
            float p1 = ex2(sc[nt][1] - mn0);
            float p2 = ex2(sc[nt][2] - mn1);
            float p3 = ex2(sc[nt][3] - mn1);
            ps0 += p0 + p1; ps1 += p2 + p3;
            __half2 hA = __floats2half2_rn(p0, p1);
            __half2 hB = __floats2half2_rn(p2, p3);
            ph[nt][0] = *(uint32_t*)&hA;
            ph[nt][1] = *(uint32_t*)&hB;
        }
        ps0 += __shfl_xor_sync(0xffffffffu, ps0, 1);
        ps0 += __shfl_xor_sync(0xffffffffu, ps0, 2);
        ps1 += __shfl_xor_sync(0xffffffffu, ps1, 1);
        ps1 += __shfl_xor_sync(0xffffffffu, ps1, 2);
        l0 = l0 * cr0 + ps0;
        l1 = l1 * cr1 + ps1;

        // ---- O rescale + O += P K (x4.trans B-loads, 2 n-tiles per ldsm) --
#pragma unroll
        for (int nt = 0; nt < 16; nt++) {
            oc[nt][0] *= cr0; oc[nt][1] *= cr0;
            oc[nt][2] *= cr1; oc[nt][3] *= cr1;
        }
#pragma unroll
        for (int kq = 0; kq < 4; kq++) {
            uint32_t pa[4] = { ph[2 * kq][0], ph[2 * kq][1],
                               ph[2 * kq + 1][0], ph[2 * kq + 1][1] };
            uint32_t krow = (uint32_t)(kq * 16 + l15);
#pragma unroll
            for (int ntp = 0; ntp < 8; ntp++) {
                uint32_t b4[4];
                ldsm_x4t(b4, kbase + krow * QLDB + (ntp * 16 + ((lane >> 4) << 3)) * 2);
                mma16816(oc[2 * ntp], pa, b4);
                mma16816(oc[2 * ntp + 1], pa, b4 + 2);
            }
        }
        CP_WAIT0();
        __syncthreads();
    }

    // ---- blend epilogue ----
    float e0 = __expf(mw[0]), e1 = __expf(mw[1]);
    float w0 = e0 / (e0 + e1), w1 = e1 / (e0 + e1);
    float il0 = 1.f / l0, il1 = 1.f / l1;
    int r0 = mb + g, r1 = mb + 8 + g;
    float* stg = (float*)smc;
    const float* ir0 = imgp + ((size_t)bb * HWP + pq0 + r0) * CO;
    const float* ir1 = imgp + ((size_t)bb * HWP + pq0 + r1) * CO;
    __syncthreads();
#pragma unroll
    for (int nt = 0; nt < 16; nt++) {
        int c = nt * 8 + 2 * t4;
        float2 i0 = *(const float2*)&ir0[c];
        float2 i1 = *(const float2*)&ir1[c];
        stg[c * 132 + r0]       = w0 * i0.x + w1 * oc[nt][0] * il0;
        stg[(c + 1) * 132 + r0] = w0 * i0.y + w1 * oc[nt][1] * il0;
        stg[c * 132 + r1]       = w0 * i1.x + w1 * oc[nt][2] * il1;
        stg[(c + 1) * 132 + r1] = w0 * i1.y + w1 * oc[nt][3] * il1;
    }
    __syncthreads();

    float* ob = out + (size_t)bb * CO * HWP;
#pragma unroll
    for (int t = 0; t < 16; t++) {
        int lin = tid + t * 256;
        int c = lin >> 5, p4 = lin & 31;
        float4 v = *(const float4*)&stg[c * 132 + p4 * 4];
        *(float4*)&ob[(size_t)c * HWP + pq0 + p4 * 4] = v;
    }
}

// ---------------------------------------------------------------------------
extern "C" void kernel_launch(void* const* d_in, const int* in_sizes, int n_in,
                              void* d_out, int out_size)
{
    const float* lidar_x = (const float*)d_in[0];
    const float* image_x = (const float*)d_in[1];
    const float* lw = (const float*)d_in[2];
    const float* lg = (const float*)d_in[3];
    const float* lb = (const float*)d_in[4];
    const float* lm = (const float*)d_in[5];
    const float* lv = (const float*)d_in[6];
    const float* iw = (const float*)d_in[7];
    const float* ig = (const float*)d_in[8];
    const float* ib = (const float*)d_in[9];
    const float* im = (const float*)d_in[10];
    const float* iv = (const float*)d_in[11];
    const float* mw = (const float*)d_in[12];
    float* out = (float*)d_out;

    float* ip = nullptr;
    __half *q16 = nullptr, *k16 = nullptr;
    cudaGetSymbolAddress((void**)&ip, g_image_proj);
    cudaGetSymbolAddress((void**)&q16, g_q16);
    cudaGetSymbolAddress((void**)&k16, g_k16);
    cudaFuncSetAttribute(proj_kernel<CLI, false, false>, cudaFuncAttributeMaxDynamicSharedMemorySize, PROJ_SMEM);
    cudaFuncSetAttribute(proj_kernel<CIM, true, true>, cudaFuncAttributeMaxDynamicSharedMemorySize, PROJ_SMEM);
    cudaFuncSetAttribute(attn_kernel, cudaFuncAttributeMaxDynamicSharedMemorySize, ATTN_SMEM);

    dim3 pgrid(HWP / 128, BB);
    proj_kernel<CLI, false, false><<<pgrid, 256, PROJ_SMEM>>>(lidar_x, lw, lg, lb, lm, lv, nullptr, k16);
    proj_kernel<CIM, true, true><<<pgrid, 256, PROJ_SMEM>>>(image_x, iw, ig, ib, im, iv, ip, q16);

    dim3 agrid(CHUNKP / 128, NCHUNK, BB);
    attn_kernel<<<agrid, 256, ATTN_SMEM>>>(q16, k16, ip, mw, out);
}